// round 1
// baseline (speedup 1.0000x reference)
#include <cuda_runtime.h>
#include <math.h>

#define B_ROWS 8192
#define D_DIM  256
#define JSPLIT 4
#define BM 128
#define BN 128
#define BK 16
#define TM 8
#define TN 8
#define JCOLS (B_ROWS / JSPLIT)   // 2048 columns per j-split
#define NJT   (JCOLS / BN)        // 16 j-tiles per split

// Scratch (device globals — no allocation allowed in kernel_launch)
__device__ float g_t2[B_ROWS];
__device__ float g_sii[B_ROWS];
__device__ float g_m[JSPLIT][B_ROWS];
__device__ float g_l[JSPLIT][B_ROWS];

// ---------------------------------------------------------------------------
// Kernel 1: per-row ||target_j||^2 and diagonal s_ii = (p_i.t_i - 0.5 t2_i)/var
// One warp per row.
__global__ void prep_kernel(const float* __restrict__ pred,
                            const float* __restrict__ target,
                            const float* __restrict__ sigma_p) {
    int row  = blockIdx.x * 8 + (threadIdx.x >> 5);
    int lane = threadIdx.x & 31;
    const float4* t4 = (const float4*)(target + (size_t)row * D_DIM);
    const float4* p4 = (const float4*)(pred   + (size_t)row * D_DIM);
    float t2 = 0.f, dp = 0.f;
    #pragma unroll
    for (int i = lane; i < D_DIM / 4; i += 32) {
        float4 t = t4[i];
        float4 p = p4[i];
        t2 += t.x * t.x + t.y * t.y + t.z * t.z + t.w * t.w;
        dp += p.x * t.x + p.y * t.y + p.z * t.z + p.w * t.w;
    }
    #pragma unroll
    for (int o = 16; o > 0; o >>= 1) {
        t2 += __shfl_xor_sync(0xffffffffu, t2, o);
        dp += __shfl_xor_sync(0xffffffffu, dp, o);
    }
    if (lane == 0) {
        float sig = *sigma_p;
        float inv_var = 1.0f / (sig * sig);
        g_t2[row]  = t2;
        g_sii[row] = (dp - 0.5f * t2) * inv_var;
    }
}

// ---------------------------------------------------------------------------
// Kernel 2: fused GEMM (pred @ target^T) + online LSE per row.
// Block: 256 threads = 16x16, each thread owns an 8x8 C sub-tile.
// Grid: (B/BM row-tiles, JSPLIT column splits). Writes partial (m, l) per row.
__global__ __launch_bounds__(256, 2)
void lse_kernel(const float* __restrict__ pred,
                const float* __restrict__ target,
                const float* __restrict__ sigma_p) {
    __shared__ __align__(16) float As[BK][BM];
    __shared__ __align__(16) float Bs[BK][BN];

    const int tid = threadIdx.x;
    const int tx  = tid & 15;   // column group
    const int ty  = tid >> 4;   // row group
    const int row0  = blockIdx.x * BM;
    const int jbase = blockIdx.y * JCOLS;

    const float sig = *sigma_p;
    const float inv_var = 1.0f / (sig * sig);

    float m_run[TM], l_run[TM];
    #pragma unroll
    for (int r = 0; r < TM; r++) { m_run[r] = -INFINITY; l_run[r] = 0.0f; }

    for (int jt = 0; jt < NJT; jt++) {
        const int col0 = jbase + jt * BN;

        float acc[TM][TN];
        #pragma unroll
        for (int r = 0; r < TM; r++)
            #pragma unroll
            for (int c = 0; c < TN; c++) acc[r][c] = 0.0f;

        for (int kt = 0; kt < D_DIM; kt += BK) {
            // Load 128x16 tiles of pred and target, stored transposed [k][row].
            // 512 float4 per tile; 256 threads -> 2 each.
            #pragma unroll
            for (int q = 0; q < 2; q++) {
                int idx = tid + q * 256;      // 0..511
                int r   = idx >> 2;           // tile row 0..127
                int c4  = idx & 3;            // which float4 along k
                float4 av = *(const float4*)(pred   + (size_t)(row0 + r) * D_DIM + kt + c4 * 4);
                As[c4 * 4 + 0][r] = av.x;
                As[c4 * 4 + 1][r] = av.y;
                As[c4 * 4 + 2][r] = av.z;
                As[c4 * 4 + 3][r] = av.w;
                float4 bv = *(const float4*)(target + (size_t)(col0 + r) * D_DIM + kt + c4 * 4);
                Bs[c4 * 4 + 0][r] = bv.x;
                Bs[c4 * 4 + 1][r] = bv.y;
                Bs[c4 * 4 + 2][r] = bv.z;
                Bs[c4 * 4 + 3][r] = bv.w;
            }
            __syncthreads();

            #pragma unroll
            for (int k = 0; k < BK; k++) {
                float a[TM], b[TN];
                #pragma unroll
                for (int i = 0; i < TM; i += 4)
                    *(float4*)&a[i] = *(const float4*)&As[k][ty * TM + i];
                #pragma unroll
                for (int i = 0; i < TN; i += 4)
                    *(float4*)&b[i] = *(const float4*)&Bs[k][tx * TN + i];
                #pragma unroll
                for (int r = 0; r < TM; r++)
                    #pragma unroll
                    for (int c = 0; c < TN; c++)
                        acc[r][c] = fmaf(a[r], b[c], acc[r][c]);
            }
            __syncthreads();
        }

        // Epilogue: s = (acc - 0.5*t2[col]) * inv_var, online LSE update.
        float t2v[TN];
        #pragma unroll
        for (int c = 0; c < TN; c += 4)
            *(float4*)&t2v[c] = *(const float4*)&g_t2[col0 + tx * TN + c];

        #pragma unroll
        for (int r = 0; r < TM; r++) {
            float s[TN];
            float mx = -INFINITY;
            #pragma unroll
            for (int c = 0; c < TN; c++) {
                s[c] = (acc[r][c] - 0.5f * t2v[c]) * inv_var;
                mx = fmaxf(mx, s[c]);
            }
            // row max across the 16 column-group lanes
            #pragma unroll
            for (int o = 1; o < 16; o <<= 1)
                mx = fmaxf(mx, __shfl_xor_sync(0xffffffffu, mx, o, 16));
            float mnew = fmaxf(m_run[r], mx);
            float sum = 0.0f;
            #pragma unroll
            for (int c = 0; c < TN; c++) sum += __expf(s[c] - mnew);
            #pragma unroll
            for (int o = 1; o < 16; o <<= 1)
                sum += __shfl_xor_sync(0xffffffffu, sum, o, 16);
            l_run[r] = l_run[r] * __expf(m_run[r] - mnew) + sum;
            m_run[r] = mnew;
        }
    }

    if (tx == 0) {
        #pragma unroll
        for (int r = 0; r < TM; r++) {
            int row = row0 + ty * TM + r;
            g_m[blockIdx.y][row] = m_run[r];
            g_l[blockIdx.y][row] = l_run[r];
        }
    }
}

// ---------------------------------------------------------------------------
// Kernel 3: merge j-split partials, combine with diag, deterministic reduce.
__global__ void reduce_kernel(const float* __restrict__ sigma_p,
                              float* __restrict__ out) {
    __shared__ double sdata[256];
    double acc = 0.0;
    for (int i = threadIdx.x; i < B_ROWS; i += 256) {
        float m = g_m[0][i];
        float l = g_l[0][i];
        #pragma unroll
        for (int s = 1; s < JSPLIT; s++) {
            float m2 = g_m[s][i], l2 = g_l[s][i];
            float mn = fmaxf(m, m2);
            l = l * __expf(m - mn) + l2 * __expf(m2 - mn);
            m = mn;
        }
        float lse = m + __logf(l);
        acc += (double)(lse - g_sii[i]);
    }
    sdata[threadIdx.x] = acc;
    __syncthreads();
    #pragma unroll
    for (int s = 128; s > 0; s >>= 1) {
        if (threadIdx.x < s) sdata[threadIdx.x] += sdata[threadIdx.x + s];
        __syncthreads();
    }
    if (threadIdx.x == 0) {
        float sig = *sigma_p;
        double scale = 2.0 * (double)sig * (double)sig / (double)B_ROWS;
        out[0] = (float)(sdata[0] * scale);
    }
}

// ---------------------------------------------------------------------------
extern "C" void kernel_launch(void* const* d_in, const int* in_sizes, int n_in,
                              void* d_out, int out_size) {
    const float* pred   = (const float*)d_in[0];
    const float* target = (const float*)d_in[1];
    const float* sigma  = (const float*)d_in[2];
    float* out = (float*)d_out;

    prep_kernel<<<B_ROWS / 8, 256>>>(pred, target, sigma);
    lse_kernel<<<dim3(B_ROWS / BM, JSPLIT), 256>>>(pred, target, sigma);
    reduce_kernel<<<1, 256>>>(sigma, out);
}

// round 3
// speedup vs baseline: 3.6630x; 3.6630x over previous
#include <cuda_runtime.h>
#include <math.h>
#include <stdint.h>

#define B_ROWS 8192
#define D_DIM  256
#define JSPLIT 32
#define BM 128
#define BN 128
#define BK 16
#define NKC (D_DIM / BK)                 // 16 k-chunks
#define NJT (B_ROWS / JSPLIT / BN)       // 2 j-tiles per CTA
#define SROWF 20                         // padded smem row stride (floats)
#define TILE_F (128 * SROWF)             // 2560 floats per tile buffer

// ---- device scratch ----
__device__ float  g_t2h[B_ROWS];                 // 0.5*||t_j||^2 / var
__device__ float  g_sii[B_ROWS];                 // (p_i.t_i - 0.5*t2_i)/var
__device__ float  g_m[JSPLIT][B_ROWS];
__device__ float  g_l[JSPLIT][B_ROWS];
__device__ double g_part[32];

// ---- helpers ----
__device__ __forceinline__ uint32_t smem_u32(const void* p) {
    uint32_t a;
    asm("{ .reg .u64 t; cvta.to.shared.u64 t, %1; cvt.u32.u64 %0, t; }" : "=r"(a) : "l"(p));
    return a;
}
__device__ __forceinline__ float to_tf32(float x) {
    float r; asm("cvt.rna.tf32.f32 %0, %1;" : "=f"(r) : "f"(x));
    return r;
}
__device__ __forceinline__ void ldsm4(uint32_t* r, uint32_t addr) {
    asm volatile("ldmatrix.sync.aligned.m8n8.x4.shared.b16 {%0,%1,%2,%3}, [%4];"
                 : "=r"(r[0]), "=r"(r[1]), "=r"(r[2]), "=r"(r[3]) : "r"(addr));
}
__device__ __forceinline__ void mma_tf32(float* d, const uint32_t* a, const uint32_t* b) {
    asm volatile(
        "mma.sync.aligned.m16n8k8.row.col.f32.tf32.tf32.f32 "
        "{%0,%1,%2,%3}, {%4,%5,%6,%7}, {%8,%9}, {%0,%1,%2,%3};"
        : "+f"(d[0]), "+f"(d[1]), "+f"(d[2]), "+f"(d[3])
        : "r"(a[0]), "r"(a[1]), "r"(a[2]), "r"(a[3]), "r"(b[0]), "r"(b[1]));
}

// ---------------------------------------------------------------------------
// Kernel 1: 0.5*t2/var and diagonal s_ii
__global__ void prep_kernel(const float* __restrict__ pred,
                            const float* __restrict__ target,
                            const float* __restrict__ sigma_p) {
    int row  = blockIdx.x * 8 + (threadIdx.x >> 5);
    int lane = threadIdx.x & 31;
    const float4* t4 = (const float4*)(target + (size_t)row * D_DIM);
    const float4* p4 = (const float4*)(pred   + (size_t)row * D_DIM);
    float t2 = 0.f, dp = 0.f;
    #pragma unroll
    for (int i = lane; i < D_DIM / 4; i += 32) {
        float4 t = t4[i]; float4 p = p4[i];
        t2 += t.x*t.x + t.y*t.y + t.z*t.z + t.w*t.w;
        dp += p.x*t.x + p.y*t.y + p.z*t.z + p.w*t.w;
    }
    #pragma unroll
    for (int o = 16; o > 0; o >>= 1) {
        t2 += __shfl_xor_sync(0xffffffffu, t2, o);
        dp += __shfl_xor_sync(0xffffffffu, dp, o);
    }
    if (lane == 0) {
        float sig = *sigma_p;
        float inv_var = 1.0f / (sig * sig);
        g_t2h[row] = 0.5f * t2 * inv_var;
        g_sii[row] = (dp - 0.5f * t2) * inv_var;
    }
}

// ---------------------------------------------------------------------------
// Kernel 2: tf32 mma.sync GEMM + fused online LSE.
// 256 threads = 8 warps (2x4 warp grid, 64x32 per warp). Grid (64, JSPLIT).
__global__ __launch_bounds__(256, 2)
void lse_mma_kernel(const float* __restrict__ pred,
                    const float* __restrict__ target,
                    const float* __restrict__ sigma_p) {
    __shared__ __align__(16) float sA[2][TILE_F];
    __shared__ __align__(16) float sB[2][TILE_F];
    __shared__ float t2s[BN];
    __shared__ float pm[4][BM];
    __shared__ float pl[4][BM];

    const int tid  = threadIdx.x;
    const int wid  = tid >> 5;
    const int lane = tid & 31;
    const int wr = wid >> 2;        // warp row (0..1): rows wr*64..+64
    const int wc = wid & 3;         // warp col (0..3): cols wc*32..+32
    const int g  = lane >> 2;       // group id
    const int t  = lane & 3;        // thread-in-group
    const int row0  = blockIdx.x * BM;
    const int jbase = blockIdx.y * (B_ROWS / JSPLIT);

    const float sig = *sigma_p;
    const float inv_var = 1.0f / (sig * sig);

    // ldmatrix per-lane address components
    const int mat = lane >> 3;
    const int lr  = lane & 7;
    const uint32_t sA0 = smem_u32(&sA[0][0]);
    const uint32_t sA1 = smem_u32(&sA[1][0]);
    const uint32_t sB0 = smem_u32(&sB[0][0]);
    const uint32_t sB1 = smem_u32(&sB[1][0]);
    // A: mat0: rows+0 k0..4 | mat1: rows+8 k0..4 | mat2: rows+0 k4..8 | mat3: rows+8 k4..8
    const uint32_t aLaneOff = (uint32_t)((wr * 64 + (mat & 1) * 8 + lr) * SROWF * 4 + (mat >> 1) * 16);
    // B: mat0: n+0 k0..4 | mat1: n+0 k4..8 | mat2: n+8 k0..4 | mat3: n+8 k4..8
    const uint32_t bLaneOff = (uint32_t)((wc * 32 + (mat >> 1) * 8 + lr) * SROWF * 4 + (mat & 1) * 16);

    const float4* pg = (const float4*)pred;    // row stride = 64 float4
    const float4* tg = (const float4*)target;

    float mrun = -INFINITY, lrun = 0.0f;       // rows owned by tid<128

    // load element mapping: per chunk 128 rows x 4 float4; 2 per thread
    const int r0l = tid >> 2, c40 = tid & 3;
    const int r1l = (tid + 256) >> 2, c41 = tid & 3;  // (tid+256)&3 == tid&3

    for (int jt = 0; jt < NJT; jt++) {
        const int col0 = jbase + jt * BN;
        if (tid < BN) t2s[tid] = g_t2h[col0 + tid];

        float acc[4][4][4];
        #pragma unroll
        for (int mf = 0; mf < 4; mf++)
            #pragma unroll
            for (int nf = 0; nf < 4; nf++)
                #pragma unroll
                for (int e = 0; e < 4; e++) acc[mf][nf][e] = 0.0f;

        // prologue: chunk 0 -> buf 0
        {
            float4 a0 = pg[(size_t)(row0 + r0l) * 64 + c40];
            float4 a1 = pg[(size_t)(row0 + r1l) * 64 + c41];
            float4 b0 = tg[(size_t)(col0 + r0l) * 64 + c40];
            float4 b1 = tg[(size_t)(col0 + r1l) * 64 + c41];
            a0.x=to_tf32(a0.x); a0.y=to_tf32(a0.y); a0.z=to_tf32(a0.z); a0.w=to_tf32(a0.w);
            a1.x=to_tf32(a1.x); a1.y=to_tf32(a1.y); a1.z=to_tf32(a1.z); a1.w=to_tf32(a1.w);
            b0.x=to_tf32(b0.x); b0.y=to_tf32(b0.y); b0.z=to_tf32(b0.z); b0.w=to_tf32(b0.w);
            b1.x=to_tf32(b1.x); b1.y=to_tf32(b1.y); b1.z=to_tf32(b1.z); b1.w=to_tf32(b1.w);
            *(float4*)&sA[0][r0l * SROWF + c40 * 4] = a0;
            *(float4*)&sA[0][r1l * SROWF + c41 * 4] = a1;
            *(float4*)&sB[0][r0l * SROWF + c40 * 4] = b0;
            *(float4*)&sB[0][r1l * SROWF + c41 * 4] = b1;
        }
        __syncthreads();

        for (int kc = 0; kc < NKC; kc++) {
            const int cur = kc & 1;
            float4 a0, a1, b0, b1;
            const bool more = (kc + 1 < NKC);
            if (more) {
                int k4 = (kc + 1) * 4;
                a0 = pg[(size_t)(row0 + r0l) * 64 + k4 + c40];
                a1 = pg[(size_t)(row0 + r1l) * 64 + k4 + c41];
                b0 = tg[(size_t)(col0 + r0l) * 64 + k4 + c40];
                b1 = tg[(size_t)(col0 + r1l) * 64 + k4 + c41];
            }

            const uint32_t aB = (cur ? sA1 : sA0) + aLaneOff;
            const uint32_t bB = (cur ? sB1 : sB0) + bLaneOff;
            #pragma unroll
            for (int ks = 0; ks < 2; ks++) {
                uint32_t af[4][4], bf[2][4];
                #pragma unroll
                for (int mf = 0; mf < 4; mf++)
                    ldsm4(af[mf], aB + (uint32_t)(mf * 16 * SROWF * 4 + ks * 32));
                #pragma unroll
                for (int np = 0; np < 2; np++)
                    ldsm4(bf[np], bB + (uint32_t)(np * 16 * SROWF * 4 + ks * 32));
                #pragma unroll
                for (int mf = 0; mf < 4; mf++)
                    #pragma unroll
                    for (int nf = 0; nf < 4; nf++)
                        mma_tf32(acc[mf][nf], af[mf], &bf[nf >> 1][(nf & 1) * 2]);
            }

            if (more) {
                a0.x=to_tf32(a0.x); a0.y=to_tf32(a0.y); a0.z=to_tf32(a0.z); a0.w=to_tf32(a0.w);
                a1.x=to_tf32(a1.x); a1.y=to_tf32(a1.y); a1.z=to_tf32(a1.z); a1.w=to_tf32(a1.w);
                b0.x=to_tf32(b0.x); b0.y=to_tf32(b0.y); b0.z=to_tf32(b0.z); b0.w=to_tf32(b0.w);
                b1.x=to_tf32(b1.x); b1.y=to_tf32(b1.y); b1.z=to_tf32(b1.z); b1.w=to_tf32(b1.w);
                float* dA = sA[cur ^ 1]; float* dB = sB[cur ^ 1];
                *(float4*)&dA[r0l * SROWF + c40 * 4] = a0;
                *(float4*)&dA[r1l * SROWF + c41 * 4] = a1;
                *(float4*)&dB[r0l * SROWF + c40 * 4] = b0;
                *(float4*)&dB[r1l * SROWF + c41 * 4] = b1;
            }
            __syncthreads();
        }

        // ---- epilogue: fused online LSE ----
        #pragma unroll
        for (int mf = 0; mf < 4; mf++) {
            #pragma unroll
            for (int h = 0; h < 2; h++) {
                float sv[8];
                float mx = -INFINITY;
                #pragma unroll
                for (int nf = 0; nf < 4; nf++)
                    #pragma unroll
                    for (int w = 0; w < 2; w++) {
                        int colt = wc * 32 + nf * 8 + 2 * t + w;
                        float s = fmaf(acc[mf][nf][h * 2 + w], inv_var, -t2s[colt]);
                        sv[nf * 2 + w] = s;
                        mx = fmaxf(mx, s);
                    }
                mx = fmaxf(mx, __shfl_xor_sync(0xffffffffu, mx, 1));
                mx = fmaxf(mx, __shfl_xor_sync(0xffffffffu, mx, 2));
                float sum = 0.0f;
                #pragma unroll
                for (int c = 0; c < 8; c++) sum += __expf(sv[c] - mx);
                sum += __shfl_xor_sync(0xffffffffu, sum, 1);
                sum += __shfl_xor_sync(0xffffffffu, sum, 2);
                if (t == 0) {
                    int rt = wr * 64 + mf * 16 + h * 8 + g;
                    pm[wc][rt] = mx;
                    pl[wc][rt] = sum;
                }
            }
        }
        __syncthreads();
        if (tid < BM) {
            float m = pm[0][tid], l = pl[0][tid];
            #pragma unroll
            for (int q = 1; q < 4; q++) {
                float m2 = pm[q][tid], l2 = pl[q][tid];
                float mn = fmaxf(m, m2);
                l = l * __expf(m - mn) + l2 * __expf(m2 - mn);
                m = mn;
            }
            float mn = fmaxf(mrun, m);
            lrun = lrun * __expf(mrun - mn) + l * __expf(m - mn);
            mrun = mn;
        }
        __syncthreads();
    }

    if (tid < BM) {
        g_m[blockIdx.y][row0 + tid] = mrun;
        g_l[blockIdx.y][row0 + tid] = lrun;
    }
}

// ---------------------------------------------------------------------------
// Kernel 3a: per-row merge of split partials, per-block deterministic sum
__global__ void reduce1_kernel(const float* __restrict__ sigma_p) {
    __shared__ double sdata[256];
    int i = blockIdx.x * 256 + threadIdx.x;   // one row per thread, 32 blocks
    double acc = 0.0;
    {
        float mmax = -INFINITY;
        #pragma unroll
        for (int s = 0; s < JSPLIT; s++) mmax = fmaxf(mmax, g_m[s][i]);
        float l = 0.0f;
        #pragma unroll
        for (int s = 0; s < JSPLIT; s++) l += g_l[s][i] * __expf(g_m[s][i] - mmax);
        float lse = mmax + __logf(l);
        acc = (double)(lse - g_sii[i]);
    }
    sdata[threadIdx.x] = acc;
    __syncthreads();
    #pragma unroll
    for (int s = 128; s > 0; s >>= 1) {
        if (threadIdx.x < s) sdata[threadIdx.x] += sdata[threadIdx.x + s];
        __syncthreads();
    }
    if (threadIdx.x == 0) g_part[blockIdx.x] = sdata[0];
}

// Kernel 3b: final deterministic combine
__global__ void reduce2_kernel(const float* __restrict__ sigma_p,
                               float* __restrict__ out) {
    if (threadIdx.x == 0) {
        double s = 0.0;
        #pragma unroll
        for (int i = 0; i < 32; i++) s += g_part[i];
        float sig = *sigma_p;
        double scale = 2.0 * (double)sig * (double)sig / (double)B_ROWS;
        out[0] = (float)(s * scale);
    }
}

// ---------------------------------------------------------------------------
extern "C" void kernel_launch(void* const* d_in, const int* in_sizes, int n_in,
                              void* d_out, int out_size) {
    const float* pred   = (const float*)d_in[0];
    const float* target = (const float*)d_in[1];
    const float* sigma  = (const float*)d_in[2];
    float* out = (float*)d_out;

    prep_kernel<<<B_ROWS / 8, 256>>>(pred, target, sigma);
    lse_mma_kernel<<<dim3(B_ROWS / BM, JSPLIT), 256>>>(pred, target, sigma);
    reduce1_kernel<<<32, 256>>>(sigma);
    reduce2_kernel<<<1, 32>>>(sigma, out);
}

// round 4
// speedup vs baseline: 4.7377x; 1.2934x over previous
#include <cuda_runtime.h>
#include <math.h>
#include <stdint.h>

#define B_ROWS 8192
#define D_DIM  256
#define JSPLIT 32
#define BM 128
#define BN 128
#define BK 32
#define NKC (D_DIM / BK)                 // 8 k-chunks
#define NJT (B_ROWS / JSPLIT / BN)       // 2 j-tiles per CTA
#define SROWF 36                         // padded smem row stride (floats)
#define TILE_F (128 * SROWF)             // floats per tile buffer

// ---- device scratch ----
__device__ float  g_predr[B_ROWS * D_DIM];       // tf32-rounded pred
__device__ float  g_targr[B_ROWS * D_DIM];       // tf32-rounded target
__device__ float  g_t2h[B_ROWS];                 // 0.5*||t_j||^2 / var
__device__ float  g_sii[B_ROWS];                 // (p_i.t_i - 0.5*t2_i)/var
__device__ float  g_m[JSPLIT][B_ROWS];
__device__ float  g_l[JSPLIT][B_ROWS];
__device__ double g_part[32];
__device__ unsigned g_cnt;

// ---- helpers ----
__device__ __forceinline__ uint32_t smem_u32(const void* p) {
    uint32_t a;
    asm("{ .reg .u64 t; cvta.to.shared.u64 t, %1; cvt.u32.u64 %0, t; }" : "=r"(a) : "l"(p));
    return a;
}
__device__ __forceinline__ float to_tf32(float x) {
    float r; asm("cvt.rna.tf32.f32 %0, %1;" : "=f"(r) : "f"(x));
    return r;
}
__device__ __forceinline__ void ldsm4(uint32_t* r, uint32_t addr) {
    asm volatile("ldmatrix.sync.aligned.m8n8.x4.shared.b16 {%0,%1,%2,%3}, [%4];"
                 : "=r"(r[0]), "=r"(r[1]), "=r"(r[2]), "=r"(r[3]) : "r"(addr));
}
__device__ __forceinline__ void mma_tf32(float* d, const uint32_t* a, const uint32_t* b) {
    asm volatile(
        "mma.sync.aligned.m16n8k8.row.col.f32.tf32.tf32.f32 "
        "{%0,%1,%2,%3}, {%4,%5,%6,%7}, {%8,%9}, {%0,%1,%2,%3};"
        : "+f"(d[0]), "+f"(d[1]), "+f"(d[2]), "+f"(d[3])
        : "r"(a[0]), "r"(a[1]), "r"(a[2]), "r"(a[3]), "r"(b[0]), "r"(b[1]));
}
__device__ __forceinline__ void cp16(uint32_t dst, const float* src) {
    asm volatile("cp.async.cg.shared.global [%0], [%1], 16;" :: "r"(dst), "l"(src));
}
#define CP_COMMIT() asm volatile("cp.async.commit_group;" ::: "memory")
#define CP_WAIT(n)  asm volatile("cp.async.wait_group %0;" :: "n"(n) : "memory")

// ---------------------------------------------------------------------------
// Kernel 1: t2h, s_ii, counter reset, and tf32-rounded copies of inputs.
// One warp per row (8 rows per 256-thread block).
__global__ void prep_kernel(const float* __restrict__ pred,
                            const float* __restrict__ target,
                            const float* __restrict__ sigma_p) {
    if (blockIdx.x == 0 && threadIdx.x == 0) g_cnt = 0;
    int row  = blockIdx.x * 8 + (threadIdx.x >> 5);
    int lane = threadIdx.x & 31;
    const float4* t4 = (const float4*)(target + (size_t)row * D_DIM);
    const float4* p4 = (const float4*)(pred   + (size_t)row * D_DIM);
    float4* pr4 = (float4*)(g_predr + (size_t)row * D_DIM);
    float4* tr4 = (float4*)(g_targr + (size_t)row * D_DIM);
    float t2 = 0.f, dp = 0.f;
    #pragma unroll
    for (int i = lane; i < D_DIM / 4; i += 32) {
        float4 t = t4[i]; float4 p = p4[i];
        t2 += t.x*t.x + t.y*t.y + t.z*t.z + t.w*t.w;
        dp += p.x*t.x + p.y*t.y + p.z*t.z + p.w*t.w;
        float4 pr, tr;
        pr.x = to_tf32(p.x); pr.y = to_tf32(p.y); pr.z = to_tf32(p.z); pr.w = to_tf32(p.w);
        tr.x = to_tf32(t.x); tr.y = to_tf32(t.y); tr.z = to_tf32(t.z); tr.w = to_tf32(t.w);
        pr4[i] = pr; tr4[i] = tr;
    }
    #pragma unroll
    for (int o = 16; o > 0; o >>= 1) {
        t2 += __shfl_xor_sync(0xffffffffu, t2, o);
        dp += __shfl_xor_sync(0xffffffffu, dp, o);
    }
    if (lane == 0) {
        float sig = *sigma_p;
        float inv_var = 1.0f / (sig * sig);
        g_t2h[row] = 0.5f * t2 * inv_var;
        g_sii[row] = (dp - 0.5f * t2) * inv_var;
    }
}

// ---------------------------------------------------------------------------
// Kernel 2: tf32 mma.sync GEMM + fused online LSE.
// 256 threads = 8 warps (2x4 warp grid, 64x32 per warp). Grid (64, JSPLIT).
// Dynamic smem: sA[2], sB[2] (BK=32 chunks, cp.async double buffer) + epilogue.
__global__ __launch_bounds__(256, 2)
void lse_mma_kernel(const float* __restrict__ sigma_p) {
    extern __shared__ __align__(16) float dsm[];
    float* sA[2] = { dsm,               dsm + TILE_F };
    float* sB[2] = { dsm + 2 * TILE_F,  dsm + 3 * TILE_F };
    float* t2s   = dsm + 4 * TILE_F;            // [128]
    float* pmb   = t2s + BN;                    // [4][128]
    float* plb   = pmb + 4 * BM;                // [4][128]

    const int tid  = threadIdx.x;
    const int wid  = tid >> 5;
    const int lane = tid & 31;
    const int wr = wid >> 2;        // warp row (0..1): rows wr*64..+64
    const int wc = wid & 3;         // warp col (0..3): cols wc*32..+32
    const int g  = lane >> 2;
    const int t  = lane & 3;
    const int row0  = blockIdx.x * BM;
    const int jbase = blockIdx.y * (B_ROWS / JSPLIT);

    const float sig = *sigma_p;
    const float inv_var = 1.0f / (sig * sig);

    // ldmatrix per-lane address components
    const int mat = lane >> 3;
    const int lr  = lane & 7;
    uint32_t sAu[2] = { smem_u32(sA[0]), smem_u32(sA[1]) };
    uint32_t sBu[2] = { smem_u32(sB[0]), smem_u32(sB[1]) };
    const uint32_t aLaneOff = (uint32_t)((wr * 64 + (mat & 1) * 8 + lr) * SROWF * 4 + (mat >> 1) * 16);
    const uint32_t bLaneOff = (uint32_t)((wc * 32 + (mat >> 1) * 8 + lr) * SROWF * 4 + (mat & 1) * 16);

    // cp.async element mapping: chunk = 128 rows x 8 float4; 1024 float4, 4/thread
    int ldr[4], ldc[4];
    uint32_t dst_off[4];
    #pragma unroll
    for (int q = 0; q < 4; q++) {
        int idx = tid + q * 256;
        ldr[q] = idx >> 3;
        ldc[q] = idx & 7;
        dst_off[q] = (uint32_t)((ldr[q] * SROWF + ldc[q] * 4) * 4);
    }

    float mrun = -INFINITY, lrun = 0.0f;

    for (int jt = 0; jt < NJT; jt++) {
        const int col0 = jbase + jt * BN;
        if (tid < BN) t2s[tid] = g_t2h[col0 + tid];

        const float* pA = g_predr + (size_t)row0 * D_DIM;
        const float* pB = g_targr + (size_t)col0 * D_DIM;

        float acc[4][4][4];
        #pragma unroll
        for (int mf = 0; mf < 4; mf++)
            #pragma unroll
            for (int nf = 0; nf < 4; nf++)
                #pragma unroll
                for (int e = 0; e < 4; e++) acc[mf][nf][e] = 0.0f;

        // prologue: issue chunk 0 into buf 0
        #pragma unroll
        for (int q = 0; q < 4; q++) {
            cp16(sAu[0] + dst_off[q], pA + (size_t)ldr[q] * D_DIM + ldc[q] * 4);
            cp16(sBu[0] + dst_off[q], pB + (size_t)ldr[q] * D_DIM + ldc[q] * 4);
        }
        CP_COMMIT();

        for (int kc = 0; kc < NKC; kc++) {
            const int cur = kc & 1;
            if (kc + 1 < NKC) {
                const int nk = (kc + 1) * BK;
                #pragma unroll
                for (int q = 0; q < 4; q++) {
                    cp16(sAu[cur ^ 1] + dst_off[q], pA + (size_t)ldr[q] * D_DIM + nk + ldc[q] * 4);
                    cp16(sBu[cur ^ 1] + dst_off[q], pB + (size_t)ldr[q] * D_DIM + nk + ldc[q] * 4);
                }
                CP_COMMIT();
                CP_WAIT(1);
            } else {
                CP_WAIT(0);
            }
            __syncthreads();

            const uint32_t aB = sAu[cur] + aLaneOff;
            const uint32_t bB = sBu[cur] + bLaneOff;
            #pragma unroll
            for (int ks = 0; ks < 4; ks++) {
                uint32_t af[4][4], bf[2][4];
                #pragma unroll
                for (int mf = 0; mf < 4; mf++)
                    ldsm4(af[mf], aB + (uint32_t)(mf * 16 * SROWF * 4 + ks * 32));
                #pragma unroll
                for (int np = 0; np < 2; np++)
                    ldsm4(bf[np], bB + (uint32_t)(np * 16 * SROWF * 4 + ks * 32));
                #pragma unroll
                for (int mf = 0; mf < 4; mf++)
                    #pragma unroll
                    for (int nf = 0; nf < 4; nf++)
                        mma_tf32(acc[mf][nf], af[mf], &bf[nf >> 1][(nf & 1) * 2]);
            }
            __syncthreads();
        }

        // ---- epilogue: fused online LSE ----
        #pragma unroll
        for (int mf = 0; mf < 4; mf++) {
            #pragma unroll
            for (int h = 0; h < 2; h++) {
                float sv[8];
                float mx = -INFINITY;
                #pragma unroll
                for (int nf = 0; nf < 4; nf++)
                    #pragma unroll
                    for (int w = 0; w < 2; w++) {
                        int colt = wc * 32 + nf * 8 + 2 * t + w;
                        float s = fmaf(acc[mf][nf][h * 2 + w], inv_var, -t2s[colt]);
                        sv[nf * 2 + w] = s;
                        mx = fmaxf(mx, s);
                    }
                mx = fmaxf(mx, __shfl_xor_sync(0xffffffffu, mx, 1));
                mx = fmaxf(mx, __shfl_xor_sync(0xffffffffu, mx, 2));
                float sum = 0.0f;
                #pragma unroll
                for (int c = 0; c < 8; c++) sum += __expf(sv[c] - mx);
                sum += __shfl_xor_sync(0xffffffffu, sum, 1);
                sum += __shfl_xor_sync(0xffffffffu, sum, 2);
                if (t == 0) {
                    int rt = wr * 64 + mf * 16 + h * 8 + g;
                    pmb[wc * BM + rt] = mx;
                    plb[wc * BM + rt] = sum;
                }
            }
        }
        __syncthreads();
        if (tid < BM) {
            float m = pmb[tid], l = plb[tid];
            #pragma unroll
            for (int q = 1; q < 4; q++) {
                float m2 = pmb[q * BM + tid], l2 = plb[q * BM + tid];
                float mn = fmaxf(m, m2);
                l = l * __expf(m - mn) + l2 * __expf(m2 - mn);
                m = mn;
            }
            float mn = fmaxf(mrun, m);
            lrun = lrun * __expf(mrun - mn) + l * __expf(m - mn);
            mrun = mn;
        }
        __syncthreads();
    }

    if (tid < BM) {
        g_m[blockIdx.y][row0 + tid] = mrun;
        g_l[blockIdx.y][row0 + tid] = lrun;
    }
}

// ---------------------------------------------------------------------------
// Kernel 3: per-row merge, per-block sum, last block does the fixed-order
// final combine (deterministic).
__global__ void reduce_kernel(const float* __restrict__ sigma_p,
                              float* __restrict__ out) {
    __shared__ double sdata[256];
    int i = blockIdx.x * 256 + threadIdx.x;
    double acc;
    {
        float mmax = -INFINITY;
        #pragma unroll
        for (int s = 0; s < JSPLIT; s++) mmax = fmaxf(mmax, g_m[s][i]);
        float l = 0.0f;
        #pragma unroll
        for (int s = 0; s < JSPLIT; s++) l += g_l[s][i] * __expf(g_m[s][i] - mmax);
        float lse = mmax + __logf(l);
        acc = (double)(lse - g_sii[i]);
    }
    sdata[threadIdx.x] = acc;
    __syncthreads();
    #pragma unroll
    for (int s = 128; s > 0; s >>= 1) {
        if (threadIdx.x < s) sdata[threadIdx.x] += sdata[threadIdx.x + s];
        __syncthreads();
    }
    if (threadIdx.x == 0) {
        g_part[blockIdx.x] = sdata[0];
        __threadfence();
        unsigned old = atomicAdd(&g_cnt, 1u);
        if (old == 31u) {
            double s = 0.0;
            #pragma unroll
            for (int b = 0; b < 32; b++) s += g_part[b];
            float sig = *sigma_p;
            double scale = 2.0 * (double)sig * (double)sig / (double)B_ROWS;
            out[0] = (float)(s * scale);
        }
    }
}

// ---------------------------------------------------------------------------
extern "C" void kernel_launch(void* const* d_in, const int* in_sizes, int n_in,
                              void* d_out, int out_size) {
    const float* pred   = (const float*)d_in[0];
    const float* target = (const float*)d_in[1];
    const float* sigma  = (const float*)d_in[2];
    float* out = (float*)d_out;

    const int smem_bytes = (4 * TILE_F + BN + 8 * BM) * 4;
    cudaFuncSetAttribute(lse_mma_kernel, cudaFuncAttributeMaxDynamicSharedMemorySize, smem_bytes);

    prep_kernel<<<B_ROWS / 8, 256>>>(pred, target, sigma);
    lse_mma_kernel<<<dim3(B_ROWS / BM, JSPLIT), 256, smem_bytes>>>(sigma);
    reduce_kernel<<<32, 256>>>(sigma, out);
}

// round 5
// speedup vs baseline: 4.9862x; 1.0525x over previous
#include <cuda_runtime.h>
#include <math.h>
#include <stdint.h>

#define B_ROWS 8192
#define D_DIM  256
#define JSPLIT 32
#define BM 128
#define BN 128
#define BK 32
#define NKC (D_DIM / BK)                 // 8 k-chunks per j-tile
#define NJT (B_ROWS / JSPLIT / BN)       // 2 j-tiles per CTA
#define NCHUNK (NJT * NKC)               // 16 chunks per CTA
#define STAGE_MAT_B (BM * BK * 4)        // 16384 bytes per matrix stage
#define STAGE_B     (2 * STAGE_MAT_B)    // A+B per stage
#define OFF_T2S  (3 * STAGE_B)           // 98304
#define OFF_PM   (OFF_T2S + 512)
#define OFF_PL   (OFF_PM + 2048)
#define SMEM_USED (OFF_PL + 2048)
#define SMEM_REQ  (SMEM_USED + 1024)     // + alignment pad

// ---- device scratch ----
__device__ float  g_predr[B_ROWS * D_DIM];       // tf32-rounded pred
__device__ float  g_targr[B_ROWS * D_DIM];       // tf32-rounded target
__device__ float  g_t2h[B_ROWS];                 // 0.5*||t_j||^2 / var
__device__ float  g_sii[B_ROWS];                 // (p_i.t_i - 0.5*t2_i)/var
__device__ float  g_m[JSPLIT][B_ROWS];
__device__ float  g_l[JSPLIT][B_ROWS];
__device__ double g_part[32];
__device__ unsigned g_cnt;

// ---- helpers ----
__device__ __forceinline__ uint32_t smem_u32(const void* p) {
    uint32_t a;
    asm("{ .reg .u64 t; cvta.to.shared.u64 t, %1; cvt.u32.u64 %0, t; }" : "=r"(a) : "l"(p));
    return a;
}
__device__ __forceinline__ float to_tf32(float x) {
    float r; asm("cvt.rna.tf32.f32 %0, %1;" : "=f"(r) : "f"(x));
    return r;
}
__device__ __forceinline__ void ldsm4(uint32_t* r, uint32_t addr) {
    asm volatile("ldmatrix.sync.aligned.m8n8.x4.shared.b16 {%0,%1,%2,%3}, [%4];"
                 : "=r"(r[0]), "=r"(r[1]), "=r"(r[2]), "=r"(r[3]) : "r"(addr));
}
__device__ __forceinline__ void mma_tf32(float* d, const uint32_t* a, const uint32_t* b) {
    asm volatile(
        "mma.sync.aligned.m16n8k8.row.col.f32.tf32.tf32.f32 "
        "{%0,%1,%2,%3}, {%4,%5,%6,%7}, {%8,%9}, {%0,%1,%2,%3};"
        : "+f"(d[0]), "+f"(d[1]), "+f"(d[2]), "+f"(d[3])
        : "r"(a[0]), "r"(a[1]), "r"(a[2]), "r"(a[3]), "r"(b[0]), "r"(b[1]));
}
__device__ __forceinline__ void cp16(uint32_t dst, const float* src) {
    asm volatile("cp.async.cg.shared.global [%0], [%1], 16;" :: "r"(dst), "l"(src));
}
#define CP_COMMIT() asm volatile("cp.async.commit_group;" ::: "memory")
#define CP_WAIT(n)  asm volatile("cp.async.wait_group %0;" :: "n"(n) : "memory")

// ---------------------------------------------------------------------------
// Kernel 1: t2h, s_ii, counter reset, tf32-rounded input copies.
__global__ void prep_kernel(const float* __restrict__ pred,
                            const float* __restrict__ target,
                            const float* __restrict__ sigma_p) {
    if (blockIdx.x == 0 && threadIdx.x == 0) g_cnt = 0;
    int row  = blockIdx.x * 8 + (threadIdx.x >> 5);
    int lane = threadIdx.x & 31;
    const float4* t4 = (const float4*)(target + (size_t)row * D_DIM);
    const float4* p4 = (const float4*)(pred   + (size_t)row * D_DIM);
    float4* pr4 = (float4*)(g_predr + (size_t)row * D_DIM);
    float4* tr4 = (float4*)(g_targr + (size_t)row * D_DIM);
    float t2 = 0.f, dp = 0.f;
    #pragma unroll
    for (int i = lane; i < D_DIM / 4; i += 32) {
        float4 t = t4[i]; float4 p = p4[i];
        t2 += t.x*t.x + t.y*t.y + t.z*t.z + t.w*t.w;
        dp += p.x*t.x + p.y*t.y + p.z*t.z + p.w*t.w;
        float4 pr, tr;
        pr.x = to_tf32(p.x); pr.y = to_tf32(p.y); pr.z = to_tf32(p.z); pr.w = to_tf32(p.w);
        tr.x = to_tf32(t.x); tr.y = to_tf32(t.y); tr.z = to_tf32(t.z); tr.w = to_tf32(t.w);
        pr4[i] = pr; tr4[i] = tr;
    }
    #pragma unroll
    for (int o = 16; o > 0; o >>= 1) {
        t2 += __shfl_xor_sync(0xffffffffu, t2, o);
        dp += __shfl_xor_sync(0xffffffffu, dp, o);
    }
    if (lane == 0) {
        float sig = *sigma_p;
        float inv_var = 1.0f / (sig * sig);
        g_t2h[row] = 0.5f * t2 * inv_var;
        g_sii[row] = (dp - 0.5f * t2) * inv_var;
    }
}

// ---------------------------------------------------------------------------
// Kernel 2: tf32 mma.sync GEMM + fused online LSE.
// 3-stage cp.async ring (swizzled smem), 1 barrier per chunk, continuous
// chunk counter across j-tiles (prefetch overlaps epilogue).
__global__ __launch_bounds__(256, 2)
void lse_mma_kernel(const float* __restrict__ sigma_p) {
    extern __shared__ __align__(16) float dsm[];
    uint32_t raw = smem_u32(dsm);
    uint32_t sb  = (raw + 1023u) & ~1023u;
    char* gb = (char*)dsm + (sb - raw);

    float* t2s = (float*)(gb + OFF_T2S);
    float* pmb = (float*)(gb + OFF_PM);
    float* plb = (float*)(gb + OFF_PL);

    const int tid  = threadIdx.x;
    const int wid  = tid >> 5;
    const int lane = tid & 31;
    const int wr = wid >> 2;
    const int wc = wid & 3;
    const int g  = lane >> 2;
    const int t  = lane & 3;
    const int row0  = blockIdx.x * BM;
    const int jbase = blockIdx.y * (B_ROWS / JSPLIT);

    const float sig = *sigma_p;
    const float inv_var = 1.0f / (sig * sig);

    const int mat = lane >> 3;
    const int lr  = lane & 7;
    // per-lane row offsets (bytes) within a stage matrix
    const uint32_t rowAoff = (uint32_t)((wr * 64 + (mat & 1) * 8 + lr) * 128);
    const uint32_t rowBoff = (uint32_t)((wc * 32 + (mat >> 1) * 8 + lr) * 128);
    // swizzled column-bytes per k-step (xor mask = lr<<4 for both A and B)
    uint32_t colA_sw[4], colB_sw[4];
    #pragma unroll
    for (int ks = 0; ks < 4; ks++) {
        colA_sw[ks] = (uint32_t)(((ks * 2 + (mat >> 1)) << 4) ^ (lr << 4));
        colB_sw[ks] = (uint32_t)(((ks * 2 + (mat & 1)) << 4) ^ (lr << 4));
    }

    // stage base addresses
    uint32_t stA[3], stB[3];
    #pragma unroll
    for (int s = 0; s < 3; s++) {
        stA[s] = sb + s * STAGE_B;
        stB[s] = sb + s * STAGE_B + STAGE_MAT_B;
    }

    // cp.async mapping: 1024 float4 per matrix stage, 4 per thread
    int ldr[4], ldc[4];
    uint32_t dst_off[4];
    #pragma unroll
    for (int q = 0; q < 4; q++) {
        int idx = tid + q * 256;
        ldr[q] = idx >> 3;
        ldc[q] = idx & 7;
        uint32_t off = (uint32_t)(ldr[q] * 128 + ldc[q] * 16);
        dst_off[q] = off ^ (((uint32_t)(ldr[q] & 7)) << 4);
    }

    const float* pA = g_predr + (size_t)row0 * D_DIM;

    // issue chunk c into stage (Au,Bu)
    auto issue = [&](int c, uint32_t Au, uint32_t Bu) {
        int kcc = c & (NKC - 1);
        const float* pAc = pA + kcc * BK;
        const float* pBc = g_targr + (size_t)(jbase + (c >> 3) * BN) * D_DIM + kcc * BK;
        #pragma unroll
        for (int q = 0; q < 4; q++) {
            cp16(Au + dst_off[q], pAc + (size_t)ldr[q] * D_DIM + ldc[q] * 4);
            cp16(Bu + dst_off[q], pBc + (size_t)ldr[q] * D_DIM + ldc[q] * 4);
        }
        CP_COMMIT();
    };

    // ring registers: current, next, next2
    uint32_t A0 = stA[0], A1 = stA[1], A2 = stA[2];
    uint32_t B0 = stB[0], B1 = stB[1], B2 = stB[2];
    issue(0, A0, B0);
    issue(1, A1, B1);

    float mrun = -INFINITY, lrun = 0.0f;

    for (int jt = 0; jt < NJT; jt++) {
        const int col0 = jbase + jt * BN;
        if (tid < BN) t2s[tid] = g_t2h[col0 + tid];

        float acc[4][4][4];
        #pragma unroll
        for (int mf = 0; mf < 4; mf++)
            #pragma unroll
            for (int nf = 0; nf < 4; nf++)
                #pragma unroll
                for (int e = 0; e < 4; e++) acc[mf][nf][e] = 0.0f;

        #pragma unroll
        for (int kc = 0; kc < NKC; kc++) {
            const int cg = jt * NKC + kc;
            if (cg == NCHUNK - 1) { CP_WAIT(0); } else { CP_WAIT(1); }
            __syncthreads();
            if (cg + 2 < NCHUNK) issue(cg + 2, A2, B2);

            const uint32_t aB = A0 + rowAoff;
            const uint32_t bB = B0 + rowBoff;
            #pragma unroll
            for (int ks = 0; ks < 4; ks++) {
                uint32_t af[4][4], bf[2][4];
                #pragma unroll
                for (int mf = 0; mf < 4; mf++)
                    ldsm4(af[mf], aB + (uint32_t)(mf * 2048) + colA_sw[ks]);
                #pragma unroll
                for (int np = 0; np < 2; np++)
                    ldsm4(bf[np], bB + (uint32_t)(np * 2048) + colB_sw[ks]);
                #pragma unroll
                for (int mf = 0; mf < 4; mf++)
                    #pragma unroll
                    for (int nf = 0; nf < 4; nf++)
                        mma_tf32(acc[mf][nf], af[mf], &bf[nf >> 1][(nf & 1) * 2]);
            }
            // rotate ring
            uint32_t tA = A0; A0 = A1; A1 = A2; A2 = tA;
            uint32_t tB = B0; B0 = B1; B1 = B2; B2 = tB;
        }

        // ---- epilogue: fused online LSE (next tile's loads already in flight) ----
        #pragma unroll
        for (int mf = 0; mf < 4; mf++) {
            #pragma unroll
            for (int h = 0; h < 2; h++) {
                float sv[8];
                float mx = -INFINITY;
                #pragma unroll
                for (int nf = 0; nf < 4; nf++)
                    #pragma unroll
                    for (int w = 0; w < 2; w++) {
                        int colt = wc * 32 + nf * 8 + 2 * t + w;
                        float s = fmaf(acc[mf][nf][h * 2 + w], inv_var, -t2s[colt]);
                        sv[nf * 2 + w] = s;
                        mx = fmaxf(mx, s);
                    }
                mx = fmaxf(mx, __shfl_xor_sync(0xffffffffu, mx, 1));
                mx = fmaxf(mx, __shfl_xor_sync(0xffffffffu, mx, 2));
                float sum = 0.0f;
                #pragma unroll
                for (int c = 0; c < 8; c++) sum += __expf(sv[c] - mx);
                sum += __shfl_xor_sync(0xffffffffu, sum, 1);
                sum += __shfl_xor_sync(0xffffffffu, sum, 2);
                if (t == 0) {
                    int rt = wr * 64 + mf * 16 + h * 8 + g;
                    pmb[wc * BM + rt] = mx;
                    plb[wc * BM + rt] = sum;
                }
            }
        }
        __syncthreads();
        if (tid < BM) {
            float m = pmb[tid], l = plb[tid];
            #pragma unroll
            for (int q = 1; q < 4; q++) {
                float m2 = pmb[q * BM + tid], l2 = plb[q * BM + tid];
                float mn = fmaxf(m, m2);
                l = l * __expf(m - mn) + l2 * __expf(m2 - mn);
                m = mn;
            }
            float mn = fmaxf(mrun, m);
            lrun = lrun * __expf(mrun - mn) + l * __expf(m - mn);
            mrun = mn;
        }
        __syncthreads();
    }

    if (tid < BM) {
        g_m[blockIdx.y][row0 + tid] = mrun;
        g_l[blockIdx.y][row0 + tid] = lrun;
    }
}

// ---------------------------------------------------------------------------
// Kernel 3: per-row merge, per-block sum, last block does fixed-order combine.
__global__ void reduce_kernel(const float* __restrict__ sigma_p,
                              float* __restrict__ out) {
    __shared__ double sdata[256];
    int i = blockIdx.x * 256 + threadIdx.x;
    double acc;
    {
        float mmax = -INFINITY;
        #pragma unroll
        for (int s = 0; s < JSPLIT; s++) mmax = fmaxf(mmax, g_m[s][i]);
        float l = 0.0f;
        #pragma unroll
        for (int s = 0; s < JSPLIT; s++) l += g_l[s][i] * __expf(g_m[s][i] - mmax);
        float lse = mmax + __logf(l);
        acc = (double)(lse - g_sii[i]);
    }
    sdata[threadIdx.x] = acc;
    __syncthreads();
    #pragma unroll
    for (int s = 128; s > 0; s >>= 1) {
        if (threadIdx.x < s) sdata[threadIdx.x] += sdata[threadIdx.x + s];
        __syncthreads();
    }
    if (threadIdx.x == 0) {
        g_part[blockIdx.x] = sdata[0];
        __threadfence();
        unsigned old = atomicAdd(&g_cnt, 1u);
        if (old == 31u) {
            double s = 0.0;
            #pragma unroll
            for (int b = 0; b < 32; b++) s += g_part[b];
            float sig = *sigma_p;
            double scale = 2.0 * (double)sig * (double)sig / (double)B_ROWS;
            out[0] = (float)(s * scale);
        }
    }
}

// ---------------------------------------------------------------------------
extern "C" void kernel_launch(void* const* d_in, const int* in_sizes, int n_in,
                              void* d_out, int out_size) {
    const float* pred   = (const float*)d_in[0];
    const float* target = (const float*)d_in[1];
    const float* sigma  = (const float*)d_in[2];
    float* out = (float*)d_out;

    cudaFuncSetAttribute(lse_mma_kernel, cudaFuncAttributeMaxDynamicSharedMemorySize, SMEM_REQ);

    prep_kernel<<<B_ROWS / 8, 256>>>(pred, target, sigma);
    lse_mma_kernel<<<dim3(B_ROWS / BM, JSPLIT), 256, SMEM_REQ>>>(sigma);
    reduce_kernel<<<32, 256>>>(sigma, out);
}

// round 6
// speedup vs baseline: 8.5898x; 1.7227x over previous
#include <cuda_runtime.h>
#include <cuda_bf16.h>
#include <math.h>
#include <stdint.h>

#define B_ROWS 8192
#define D_DIM  256
#define JSPLIT 32
#define BM 128
#define BN 128
#define BK 64
#define NKC (D_DIM / BK)                 // 4 k-chunks per j-tile
#define NJT (B_ROWS / JSPLIT / BN)       // 2 j-tiles per CTA
#define NCHUNK (NJT * NKC)               // 8 chunks per CTA
#define STAGE_MAT_B (BM * BK * 2)        // 16384 bytes per matrix stage (bf16)
#define STAGE_B     (2 * STAGE_MAT_B)    // A+B per stage
#define OFF_T2S  (3 * STAGE_B)           // 98304
#define OFF_PM   (OFF_T2S + 512)
#define OFF_PL   (OFF_PM + 2048)
#define SMEM_USED (OFF_PL + 2048)
#define SMEM_REQ  (SMEM_USED + 1024)

// ---- device scratch ----
__device__ __nv_bfloat16 g_predh[B_ROWS * D_DIM];
__device__ __nv_bfloat16 g_targh[B_ROWS * D_DIM];
__device__ float  g_t2h[B_ROWS];                 // 0.5*||t_j||^2 / var (rounded vals)
__device__ float  g_sii[B_ROWS];                 // (p_i.t_i - 0.5*t2_i)/var (rounded vals)
__device__ float  g_m[JSPLIT][B_ROWS];
__device__ float  g_l[JSPLIT][B_ROWS];
__device__ double g_part[32];
__device__ unsigned g_cnt;

// ---- helpers ----
__device__ __forceinline__ uint32_t smem_u32(const void* p) {
    uint32_t a;
    asm("{ .reg .u64 t; cvta.to.shared.u64 t, %1; cvt.u32.u64 %0, t; }" : "=r"(a) : "l"(p));
    return a;
}
__device__ __forceinline__ void ldsm4(uint32_t* r, uint32_t addr) {
    asm volatile("ldmatrix.sync.aligned.m8n8.x4.shared.b16 {%0,%1,%2,%3}, [%4];"
                 : "=r"(r[0]), "=r"(r[1]), "=r"(r[2]), "=r"(r[3]) : "r"(addr));
}
__device__ __forceinline__ void mma_bf16(float* d, const uint32_t* a, const uint32_t* b) {
    asm volatile(
        "mma.sync.aligned.m16n8k16.row.col.f32.bf16.bf16.f32 "
        "{%0,%1,%2,%3}, {%4,%5,%6,%7}, {%8,%9}, {%0,%1,%2,%3};"
        : "+f"(d[0]), "+f"(d[1]), "+f"(d[2]), "+f"(d[3])
        : "r"(a[0]), "r"(a[1]), "r"(a[2]), "r"(a[3]), "r"(b[0]), "r"(b[1]));
}
__device__ __forceinline__ void cp16(uint32_t dst, const void* src) {
    asm volatile("cp.async.cg.shared.global [%0], [%1], 16;" :: "r"(dst), "l"(src));
}
#define CP_COMMIT() asm volatile("cp.async.commit_group;" ::: "memory")
#define CP_WAIT(n)  asm volatile("cp.async.wait_group %0;" :: "n"(n) : "memory")

// ---------------------------------------------------------------------------
// Kernel 1: bf16-rounded copies; t2h + s_ii computed FROM the rounded values
// (fp32 math) so the diagonal cancels consistently against the bf16 GEMM.
__global__ void prep_kernel(const float* __restrict__ pred,
                            const float* __restrict__ target,
                            const float* __restrict__ sigma_p) {
    if (blockIdx.x == 0 && threadIdx.x == 0) g_cnt = 0;
    int row  = blockIdx.x * 8 + (threadIdx.x >> 5);
    int lane = threadIdx.x & 31;
    const float4* t4 = (const float4*)(target + (size_t)row * D_DIM);
    const float4* p4 = (const float4*)(pred   + (size_t)row * D_DIM);
    __nv_bfloat162* ph = (__nv_bfloat162*)(g_predh + (size_t)row * D_DIM);
    __nv_bfloat162* th = (__nv_bfloat162*)(g_targh + (size_t)row * D_DIM);
    float t2 = 0.f, dp = 0.f;
    #pragma unroll
    for (int i = lane; i < D_DIM / 4; i += 32) {
        float4 t = t4[i]; float4 p = p4[i];
        __nv_bfloat162 p0 = __floats2bfloat162_rn(p.x, p.y);
        __nv_bfloat162 p1 = __floats2bfloat162_rn(p.z, p.w);
        __nv_bfloat162 t0 = __floats2bfloat162_rn(t.x, t.y);
        __nv_bfloat162 t1 = __floats2bfloat162_rn(t.z, t.w);
        ph[i * 2] = p0; ph[i * 2 + 1] = p1;
        th[i * 2] = t0; th[i * 2 + 1] = t1;
        float tx = __bfloat162float(t0.x), ty = __bfloat162float(t0.y);
        float tz = __bfloat162float(t1.x), tw = __bfloat162float(t1.y);
        float px = __bfloat162float(p0.x), py = __bfloat162float(p0.y);
        float pz = __bfloat162float(p1.x), pw = __bfloat162float(p1.y);
        t2 += tx*tx + ty*ty + tz*tz + tw*tw;
        dp += px*tx + py*ty + pz*tz + pw*tw;
    }
    #pragma unroll
    for (int o = 16; o > 0; o >>= 1) {
        t2 += __shfl_xor_sync(0xffffffffu, t2, o);
        dp += __shfl_xor_sync(0xffffffffu, dp, o);
    }
    if (lane == 0) {
        float sig = *sigma_p;
        float inv_var = 1.0f / (sig * sig);
        g_t2h[row] = 0.5f * t2 * inv_var;
        g_sii[row] = (dp - 0.5f * t2) * inv_var;
    }
}

// ---------------------------------------------------------------------------
// Kernel 2: bf16 mma.sync m16n8k16 GEMM + fused online LSE.
// 3-stage cp.async ring, swizzled 128B-row smem, 1 barrier per chunk.
__global__ __launch_bounds__(256, 2)
void lse_mma_kernel(const float* __restrict__ sigma_p) {
    extern __shared__ __align__(16) float dsm[];
    uint32_t raw = smem_u32(dsm);
    uint32_t sb  = (raw + 1023u) & ~1023u;
    char* gb = (char*)dsm + (sb - raw);

    float* t2s = (float*)(gb + OFF_T2S);
    float* pmb = (float*)(gb + OFF_PM);
    float* plb = (float*)(gb + OFF_PL);

    const int tid  = threadIdx.x;
    const int wid  = tid >> 5;
    const int lane = tid & 31;
    const int wr = wid >> 2;
    const int wc = wid & 3;
    const int g  = lane >> 2;
    const int t  = lane & 3;
    const int row0  = blockIdx.x * BM;
    const int jbase = blockIdx.y * (B_ROWS / JSPLIT);

    const float sig = *sigma_p;
    const float inv_var = 1.0f / (sig * sig);

    const int mat = lane >> 3;
    const int lr  = lane & 7;
    // rows are 64 bf16 = 128 bytes; same addressing as the tf32 version.
    const uint32_t rowAoff = (uint32_t)((wr * 64 + (mat & 1) * 8 + lr) * 128);
    const uint32_t rowBoff = (uint32_t)((wc * 32 + (mat >> 1) * 8 + lr) * 128);
    uint32_t colA_sw[4], colB_sw[4];
    #pragma unroll
    for (int ks = 0; ks < 4; ks++) {
        colA_sw[ks] = (uint32_t)(((ks * 2 + (mat >> 1)) << 4) ^ (lr << 4));
        colB_sw[ks] = (uint32_t)(((ks * 2 + (mat & 1)) << 4) ^ (lr << 4));
    }

    uint32_t stA[3], stB[3];
    #pragma unroll
    for (int s = 0; s < 3; s++) {
        stA[s] = sb + s * STAGE_B;
        stB[s] = sb + s * STAGE_B + STAGE_MAT_B;
    }

    // cp.async mapping: 1024 x 16B per matrix stage, 4 per thread
    int ldr[4], ldc[4];
    uint32_t dst_off[4];
    #pragma unroll
    for (int q = 0; q < 4; q++) {
        int idx = tid + q * 256;
        ldr[q] = idx >> 3;
        ldc[q] = idx & 7;
        uint32_t off = (uint32_t)(ldr[q] * 128 + ldc[q] * 16);
        dst_off[q] = off ^ (((uint32_t)(ldr[q] & 7)) << 4);
    }

    const __nv_bfloat16* pA = g_predh + (size_t)row0 * D_DIM;

    auto issue = [&](int c, uint32_t Au, uint32_t Bu) {
        int kcc = c & (NKC - 1);
        const __nv_bfloat16* pAc = pA + kcc * BK;
        const __nv_bfloat16* pBc = g_targh + (size_t)(jbase + (c >> 2) * BN) * D_DIM + kcc * BK;
        #pragma unroll
        for (int q = 0; q < 4; q++) {
            cp16(Au + dst_off[q], pAc + (size_t)ldr[q] * D_DIM + ldc[q] * 8);
            cp16(Bu + dst_off[q], pBc + (size_t)ldr[q] * D_DIM + ldc[q] * 8);
        }
        CP_COMMIT();
    };

    uint32_t A0 = stA[0], A1 = stA[1], A2 = stA[2];
    uint32_t B0 = stB[0], B1 = stB[1], B2 = stB[2];
    issue(0, A0, B0);
    issue(1, A1, B1);

    float mrun = -INFINITY, lrun = 0.0f;

    for (int jt = 0; jt < NJT; jt++) {
        const int col0 = jbase + jt * BN;
        if (tid < BN) t2s[tid] = g_t2h[col0 + tid];

        float acc[4][4][4];
        #pragma unroll
        for (int mf = 0; mf < 4; mf++)
            #pragma unroll
            for (int nf = 0; nf < 4; nf++)
                #pragma unroll
                for (int e = 0; e < 4; e++) acc[mf][nf][e] = 0.0f;

        #pragma unroll
        for (int kc = 0; kc < NKC; kc++) {
            const int cg = jt * NKC + kc;
            if (cg == NCHUNK - 1) { CP_WAIT(0); } else { CP_WAIT(1); }
            __syncthreads();
            if (cg + 2 < NCHUNK) issue(cg + 2, A2, B2);

            const uint32_t aB = A0 + rowAoff;
            const uint32_t bB = B0 + rowBoff;
            #pragma unroll
            for (int ks = 0; ks < 4; ks++) {
                uint32_t af[4][4], bf[2][4];
                #pragma unroll
                for (int mf = 0; mf < 4; mf++)
                    ldsm4(af[mf], aB + (uint32_t)(mf * 2048) + colA_sw[ks]);
                #pragma unroll
                for (int np = 0; np < 2; np++)
                    ldsm4(bf[np], bB + (uint32_t)(np * 2048) + colB_sw[ks]);
                #pragma unroll
                for (int mf = 0; mf < 4; mf++)
                    #pragma unroll
                    for (int nf = 0; nf < 4; nf++)
                        mma_bf16(acc[mf][nf], af[mf], &bf[nf >> 1][(nf & 1) * 2]);
            }
            uint32_t tA = A0; A0 = A1; A1 = A2; A2 = tA;
            uint32_t tB = B0; B0 = B1; B1 = B2; B2 = tB;
        }

        // ---- epilogue: fused online LSE ----
        #pragma unroll
        for (int mf = 0; mf < 4; mf++) {
            #pragma unroll
            for (int h = 0; h < 2; h++) {
                float sv[8];
                float mx = -INFINITY;
                #pragma unroll
                for (int nf = 0; nf < 4; nf++)
                    #pragma unroll
                    for (int w = 0; w < 2; w++) {
                        int colt = wc * 32 + nf * 8 + 2 * t + w;
                        float s = fmaf(acc[mf][nf][h * 2 + w], inv_var, -t2s[colt]);
                        sv[nf * 2 + w] = s;
                        mx = fmaxf(mx, s);
                    }
                mx = fmaxf(mx, __shfl_xor_sync(0xffffffffu, mx, 1));
                mx = fmaxf(mx, __shfl_xor_sync(0xffffffffu, mx, 2));
                float sum = 0.0f;
                #pragma unroll
                for (int c = 0; c < 8; c++) sum += __expf(sv[c] - mx);
                sum += __shfl_xor_sync(0xffffffffu, sum, 1);
                sum += __shfl_xor_sync(0xffffffffu, sum, 2);
                if (t == 0) {
                    int rt = wr * 64 + mf * 16 + h * 8 + g;
                    pmb[wc * BM + rt] = mx;
                    plb[wc * BM + rt] = sum;
                }
            }
        }
        __syncthreads();
        if (tid < BM) {
            float m = pmb[tid], l = plb[tid];
            #pragma unroll
            for (int q = 1; q < 4; q++) {
                float m2 = pmb[q * BM + tid], l2 = plb[q * BM + tid];
                float mn = fmaxf(m, m2);
                l = l * __expf(m - mn) + l2 * __expf(m2 - mn);
                m = mn;
            }
            float mn = fmaxf(mrun, m);
            lrun = lrun * __expf(mrun - mn) + l * __expf(m - mn);
            mrun = mn;
        }
        __syncthreads();
    }

    if (tid < BM) {
        g_m[blockIdx.y][row0 + tid] = mrun;
        g_l[blockIdx.y][row0 + tid] = lrun;
    }
}

// ---------------------------------------------------------------------------
// Kernel 3: per-row merge, per-block sum, last block fixed-order combine.
__global__ void reduce_kernel(const float* __restrict__ sigma_p,
                              float* __restrict__ out) {
    __shared__ double sdata[256];
    int i = blockIdx.x * 256 + threadIdx.x;
    double acc;
    {
        float mmax = -INFINITY;
        #pragma unroll
        for (int s = 0; s < JSPLIT; s++) mmax = fmaxf(mmax, g_m[s][i]);
        float l = 0.0f;
        #pragma unroll
        for (int s = 0; s < JSPLIT; s++) l += g_l[s][i] * __expf(g_m[s][i] - mmax);
        float lse = mmax + __logf(l);
        acc = (double)(lse - g_sii[i]);
    }
    sdata[threadIdx.x] = acc;
    __syncthreads();
    #pragma unroll
    for (int s = 128; s > 0; s >>= 1) {
        if (threadIdx.x < s) sdata[threadIdx.x] += sdata[threadIdx.x + s];
        __syncthreads();
    }
    if (threadIdx.x == 0) {
        g_part[blockIdx.x] = sdata[0];
        __threadfence();
        unsigned old = atomicAdd(&g_cnt, 1u);
        if (old == 31u) {
            double s = 0.0;
            #pragma unroll
            for (int b = 0; b < 32; b++) s += g_part[b];
            float sig = *sigma_p;
            double scale = 2.0 * (double)sig * (double)sig / (double)B_ROWS;
            out[0] = (float)(s * scale);
        }
    }
}

// ---------------------------------------------------------------------------
extern "C" void kernel_launch(void* const* d_in, const int* in_sizes, int n_in,
                              void* d_out, int out_size) {
    const float* pred   = (const float*)d_in[0];
    const float* target = (const float*)d_in[1];
    const float* sigma  = (const float*)d_in[2];
    float* out = (float*)d_out;

    cudaFuncSetAttribute(lse_mma_kernel, cudaFuncAttributeMaxDynamicSharedMemorySize, SMEM_REQ);

    prep_kernel<<<B_ROWS / 8, 256>>>(pred, target, sigma);
    lse_mma_kernel<<<dim3(B_ROWS / BM, JSPLIT), 256, SMEM_REQ>>>(sigma);
    reduce_kernel<<<32, 256>>>(sigma, out);
}

// round 7
// speedup vs baseline: 9.3626x; 1.0900x over previous
#include <cuda_runtime.h>
#include <cuda_bf16.h>
#include <math.h>
#include <stdint.h>

#define B_ROWS 8192
#define D_DIM  256
#define JSPLIT 32
#define BM 128
#define BN 128
#define BK 64
#define NKC (D_DIM / BK)                 // 4 k-chunks per j-tile
#define NJT (B_ROWS / JSPLIT / BN)       // 2 j-tiles per CTA
#define NCHUNK (NJT * NKC)               // 8 chunks per CTA
#define STAGE_MAT_B (BM * BK * 2)        // 16384 bytes per matrix stage (bf16)
#define STAGE_B     (2 * STAGE_MAT_B)    // A+B per stage = 32768
#define OFF_T2S  (3 * STAGE_B)           // 98304
#define OFF_PM   (OFF_T2S + 512)
#define OFF_PL   (OFF_PM + 1024)
#define SMEM_USED (OFF_PL + 1024)
#define SMEM_REQ  (SMEM_USED + 1024)

// ---- device scratch ----
__device__ __nv_bfloat16 g_predh[B_ROWS * D_DIM];
__device__ __nv_bfloat16 g_targh[B_ROWS * D_DIM];
__device__ float  g_t2h[B_ROWS];
__device__ float  g_sii[B_ROWS];
__device__ float  g_m[JSPLIT][B_ROWS];
__device__ float  g_l[JSPLIT][B_ROWS];
__device__ double g_part[32];
__device__ unsigned g_cnt;

// ---- helpers ----
__device__ __forceinline__ uint32_t smem_u32(const void* p) {
    uint32_t a;
    asm("{ .reg .u64 t; cvta.to.shared.u64 t, %1; cvt.u32.u64 %0, t; }" : "=r"(a) : "l"(p));
    return a;
}
__device__ __forceinline__ void ldsm4(uint32_t* r, uint32_t addr) {
    asm volatile("ldmatrix.sync.aligned.m8n8.x4.shared.b16 {%0,%1,%2,%3}, [%4];"
                 : "=r"(r[0]), "=r"(r[1]), "=r"(r[2]), "=r"(r[3]) : "r"(addr));
}
__device__ __forceinline__ void mma_bf16(float* d, const uint32_t* a, const uint32_t* b) {
    asm volatile(
        "mma.sync.aligned.m16n8k16.row.col.f32.bf16.bf16.f32 "
        "{%0,%1,%2,%3}, {%4,%5,%6,%7}, {%8,%9}, {%0,%1,%2,%3};"
        : "+f"(d[0]), "+f"(d[1]), "+f"(d[2]), "+f"(d[3])
        : "r"(a[0]), "r"(a[1]), "r"(a[2]), "r"(a[3]), "r"(b[0]), "r"(b[1]));
}
__device__ __forceinline__ void cp16(uint32_t dst, const void* src) {
    asm volatile("cp.async.cg.shared.global [%0], [%1], 16;" :: "r"(dst), "l"(src));
}
#define CP_COMMIT() asm volatile("cp.async.commit_group;" ::: "memory")
#define CP_WAIT(n)  asm volatile("cp.async.wait_group %0;" :: "n"(n) : "memory")

// ---------------------------------------------------------------------------
// Kernel 1: bf16-rounded copies; t2h + s_ii from the ROUNDED values so the
// diagonal cancels consistently against the bf16 GEMM.
__global__ void prep_kernel(const float* __restrict__ pred,
                            const float* __restrict__ target,
                            const float* __restrict__ sigma_p) {
    if (blockIdx.x == 0 && threadIdx.x == 0) g_cnt = 0;
    int row  = blockIdx.x * 8 + (threadIdx.x >> 5);
    int lane = threadIdx.x & 31;
    const float4* t4 = (const float4*)(target + (size_t)row * D_DIM);
    const float4* p4 = (const float4*)(pred   + (size_t)row * D_DIM);
    __nv_bfloat162* ph = (__nv_bfloat162*)(g_predh + (size_t)row * D_DIM);
    __nv_bfloat162* th = (__nv_bfloat162*)(g_targh + (size_t)row * D_DIM);
    float t2 = 0.f, dp = 0.f;
    #pragma unroll
    for (int i = lane; i < D_DIM / 4; i += 32) {
        float4 t = t4[i]; float4 p = p4[i];
        __nv_bfloat162 p0 = __floats2bfloat162_rn(p.x, p.y);
        __nv_bfloat162 p1 = __floats2bfloat162_rn(p.z, p.w);
        __nv_bfloat162 t0 = __floats2bfloat162_rn(t.x, t.y);
        __nv_bfloat162 t1 = __floats2bfloat162_rn(t.z, t.w);
        ph[i * 2] = p0; ph[i * 2 + 1] = p1;
        th[i * 2] = t0; th[i * 2 + 1] = t1;
        float tx = __bfloat162float(t0.x), ty = __bfloat162float(t0.y);
        float tz = __bfloat162float(t1.x), tw = __bfloat162float(t1.y);
        float px = __bfloat162float(p0.x), py = __bfloat162float(p0.y);
        float pz = __bfloat162float(p1.x), pw = __bfloat162float(p1.y);
        t2 += tx*tx + ty*ty + tz*tz + tw*tw;
        dp += px*tx + py*ty + pz*tz + pw*tw;
    }
    #pragma unroll
    for (int o = 16; o > 0; o >>= 1) {
        t2 += __shfl_xor_sync(0xffffffffu, t2, o);
        dp += __shfl_xor_sync(0xffffffffu, dp, o);
    }
    if (lane == 0) {
        float sig = *sigma_p;
        float inv_var = 1.0f / (sig * sig);
        g_t2h[row] = 0.5f * t2 * inv_var;
        g_sii[row] = (dp - 0.5f * t2) * inv_var;
    }
}

// ---------------------------------------------------------------------------
// Kernel 2: bf16 mma.sync GEMM + fused online LSE.
// 4 warps (2x2 grid of 64x64 warp tiles), 3-stage cp.async ring, swizzled smem.
__global__ __launch_bounds__(128, 2)
void lse_mma_kernel(const float* __restrict__ sigma_p) {
    extern __shared__ __align__(16) float dsm[];
    uint32_t raw = smem_u32(dsm);
    uint32_t sb  = (raw + 1023u) & ~1023u;
    char* gb = (char*)dsm + (sb - raw);

    float* t2s = (float*)(gb + OFF_T2S);
    float* pmb = (float*)(gb + OFF_PM);    // [2][128]
    float* plb = (float*)(gb + OFF_PL);

    const int tid  = threadIdx.x;
    const int wid  = tid >> 5;
    const int lane = tid & 31;
    const int wr = wid >> 1;        // 0..1: rows wr*64..+64
    const int wc = wid & 1;         // 0..1: cols wc*64..+64
    const int g  = lane >> 2;
    const int t  = lane & 3;
    const int row0  = blockIdx.x * BM;
    const int jbase = blockIdx.y * (B_ROWS / JSPLIT);

    const float sig = *sigma_p;
    const float inv_var = 1.0f / (sig * sig);

    const int mat = lane >> 3;
    const int lr  = lane & 7;
    const uint32_t rowAoff = (uint32_t)((wr * 64 + (mat & 1) * 8 + lr) * 128);
    const uint32_t rowBoff = (uint32_t)((wc * 64 + (mat >> 1) * 8 + lr) * 128);
    uint32_t colA_sw[4], colB_sw[4];
    #pragma unroll
    for (int ks = 0; ks < 4; ks++) {
        colA_sw[ks] = (uint32_t)(((ks * 2 + (mat >> 1)) << 4) ^ (lr << 4));
        colB_sw[ks] = (uint32_t)(((ks * 2 + (mat & 1)) << 4) ^ (lr << 4));
    }

    uint32_t stA[3], stB[3];
    #pragma unroll
    for (int s = 0; s < 3; s++) {
        stA[s] = sb + s * STAGE_B;
        stB[s] = sb + s * STAGE_B + STAGE_MAT_B;
    }

    // cp.async mapping: 1024 x 16B units per matrix stage, 8 per thread
    int ldr[8], ldc[8];
    uint32_t dst_off[8];
    #pragma unroll
    for (int q = 0; q < 8; q++) {
        int idx = tid + q * 128;
        ldr[q] = idx >> 3;
        ldc[q] = idx & 7;
        uint32_t off = (uint32_t)(ldr[q] * 128 + ldc[q] * 16);
        dst_off[q] = off ^ (((uint32_t)(ldr[q] & 7)) << 4);
    }

    const __nv_bfloat16* pA = g_predh + (size_t)row0 * D_DIM;

    auto issue = [&](int c, uint32_t Au, uint32_t Bu) {
        int kcc = c & (NKC - 1);
        const __nv_bfloat16* pAc = pA + kcc * BK;
        const __nv_bfloat16* pBc = g_targh + (size_t)(jbase + (c >> 2) * BN) * D_DIM + kcc * BK;
        #pragma unroll
        for (int q = 0; q < 8; q++)
            cp16(Au + dst_off[q], pAc + (size_t)ldr[q] * D_DIM + ldc[q] * 8);
        #pragma unroll
        for (int q = 0; q < 8; q++)
            cp16(Bu + dst_off[q], pBc + (size_t)ldr[q] * D_DIM + ldc[q] * 8);
        CP_COMMIT();
    };

    uint32_t A0 = stA[0], A1 = stA[1], A2 = stA[2];
    uint32_t B0 = stB[0], B1 = stB[1], B2 = stB[2];
    issue(0, A0, B0);
    issue(1, A1, B1);

    float mrun = -INFINITY, lrun = 0.0f;

    for (int jt = 0; jt < NJT; jt++) {
        const int col0 = jbase + jt * BN;
        t2s[tid] = g_t2h[col0 + tid];

        float acc[4][8][4];
        #pragma unroll
        for (int mf = 0; mf < 4; mf++)
            #pragma unroll
            for (int nf = 0; nf < 8; nf++)
                #pragma unroll
                for (int e = 0; e < 4; e++) acc[mf][nf][e] = 0.0f;

        #pragma unroll
        for (int kc = 0; kc < NKC; kc++) {
            const int cg = jt * NKC + kc;
            if (cg == NCHUNK - 1) { CP_WAIT(0); } else { CP_WAIT(1); }
            __syncthreads();
            if (cg + 2 < NCHUNK) issue(cg + 2, A2, B2);

            const uint32_t aB = A0 + rowAoff;
            const uint32_t bB = B0 + rowBoff;
            #pragma unroll
            for (int ks = 0; ks < 4; ks++) {
                uint32_t af[4][4], bf[4][4];
                #pragma unroll
                for (int mf = 0; mf < 4; mf++)
                    ldsm4(af[mf], aB + (uint32_t)(mf * 2048) + colA_sw[ks]);
                #pragma unroll
                for (int np = 0; np < 4; np++)
                    ldsm4(bf[np], bB + (uint32_t)(np * 2048) + colB_sw[ks]);
                #pragma unroll
                for (int mf = 0; mf < 4; mf++)
                    #pragma unroll
                    for (int nf = 0; nf < 8; nf++)
                        mma_bf16(acc[mf][nf], af[mf], &bf[nf >> 1][(nf & 1) * 2]);
            }
            uint32_t tA = A0; A0 = A1; A1 = A2; A2 = tA;
            uint32_t tB = B0; B0 = B1; B1 = B2; B2 = tB;
        }

        // ---- epilogue: fused online LSE ----
        #pragma unroll
        for (int mf = 0; mf < 4; mf++) {
            #pragma unroll
            for (int h = 0; h < 2; h++) {
                float sv[16];
                float mx = -INFINITY;
                #pragma unroll
                for (int nf = 0; nf < 8; nf++)
                    #pragma unroll
                    for (int w = 0; w < 2; w++) {
                        int colt = wc * 64 + nf * 8 + 2 * t + w;
                        float s = fmaf(acc[mf][nf][h * 2 + w], inv_var, -t2s[colt]);
                        sv[nf * 2 + w] = s;
                        mx = fmaxf(mx, s);
                    }
                mx = fmaxf(mx, __shfl_xor_sync(0xffffffffu, mx, 1));
                mx = fmaxf(mx, __shfl_xor_sync(0xffffffffu, mx, 2));
                float sum = 0.0f;
                #pragma unroll
                for (int c = 0; c < 16; c++) sum += __expf(sv[c] - mx);
                sum += __shfl_xor_sync(0xffffffffu, sum, 1);
                sum += __shfl_xor_sync(0xffffffffu, sum, 2);
                if (t == 0) {
                    int rt = wr * 64 + mf * 16 + h * 8 + g;
                    pmb[wc * BM + rt] = mx;
                    plb[wc * BM + rt] = sum;
                }
            }
        }
        __syncthreads();
        {
            float m = pmb[tid], l = plb[tid];
            float m2 = pmb[BM + tid], l2 = plb[BM + tid];
            float mn = fmaxf(m, m2);
            l = l * __expf(m - mn) + l2 * __expf(m2 - mn);
            m = mn;
            float mn2 = fmaxf(mrun, m);
            lrun = lrun * __expf(mrun - mn2) + l * __expf(m - mn2);
            mrun = mn2;
        }
        __syncthreads();
    }

    g_m[blockIdx.y][row0 + tid] = mrun;
    g_l[blockIdx.y][row0 + tid] = lrun;
}

// ---------------------------------------------------------------------------
// Kernel 3: per-row merge, per-block sum, last block fixed-order combine.
__global__ void reduce_kernel(const float* __restrict__ sigma_p,
                              float* __restrict__ out) {
    __shared__ double sdata[256];
    int i = blockIdx.x * 256 + threadIdx.x;
    double acc;
    {
        float mmax = -INFINITY;
        #pragma unroll
        for (int s = 0; s < JSPLIT; s++) mmax = fmaxf(mmax, g_m[s][i]);
        float l = 0.0f;
        #pragma unroll
        for (int s = 0; s < JSPLIT; s++) l += g_l[s][i] * __expf(g_m[s][i] - mmax);
        float lse = mmax + __logf(l);
        acc = (double)(lse - g_sii[i]);
    }
    sdata[threadIdx.x] = acc;
    __syncthreads();
    #pragma unroll
    for (int s = 128; s > 0; s >>= 1) {
        if (threadIdx.x < s) sdata[threadIdx.x] += sdata[threadIdx.x + s];
        __syncthreads();
    }
    if (threadIdx.x == 0) {
        g_part[blockIdx.x] = sdata[0];
        __threadfence();
        unsigned old = atomicAdd(&g_cnt, 1u);
        if (old == 31u) {
            double s = 0.0;
            #pragma unroll
            for (int b = 0; b < 32; b++) s += g_part[b];
            float sig = *sigma_p;
            double scale = 2.0 * (double)sig * (double)sig / (double)B_ROWS;
            out[0] = (float)(s * scale);
        }
    }
}

// ---------------------------------------------------------------------------
extern "C" void kernel_launch(void* const* d_in, const int* in_sizes, int n_in,
                              void* d_out, int out_size) {
    const float* pred   = (const float*)d_in[0];
    const float* target = (const float*)d_in[1];
    const float* sigma  = (const float*)d_in[2];
    float* out = (float*)d_out;

    cudaFuncSetAttribute(lse_mma_kernel, cudaFuncAttributeMaxDynamicSharedMemorySize, SMEM_REQ);

    prep_kernel<<<B_ROWS / 8, 256>>>(pred, target, sigma);
    lse_mma_kernel<<<dim3(B_ROWS / BM, JSPLIT), 128, SMEM_REQ>>>(sigma);
    reduce_kernel<<<32, 256>>>(sigma, out);
}

// round 8
// speedup vs baseline: 9.5490x; 1.0199x over previous
#include <cuda_runtime.h>
#include <cuda_bf16.h>
#include <math.h>
#include <stdint.h>

#define B_ROWS 8192
#define D_DIM  256
#define JSPLIT 32                        // column splits of 256 cols each
#define NSPLIT (JSPLIT * 2)              // per-64-col splits in g_m/g_l
#define BM 128
#define BN 128
#define BK 64
#define NKC (D_DIM / BK)                 // 4 k-chunks per j-tile
#define NJT 2                            // j-tiles per CTA
#define NCHUNK (NJT * NKC)               // 8 chunks per CTA
#define A_BYTES   (BM * D_DIM * 2)       // 65536: A resident (4 chunks x 16KB)
#define STAGE_B   (BN * BK * 2)          // 16384 per B stage
#define SMEM_REQ  (A_BYTES + 3 * STAGE_B)  // 114688 = 112KB exactly
#define LOG2E 1.4426950408889634f
#define LN2   0.6931471805599453f

// ---- device scratch ----
__device__ __nv_bfloat16 g_predh[B_ROWS * D_DIM];
__device__ __nv_bfloat16 g_targh[B_ROWS * D_DIM];
__device__ float  g_t2l[B_ROWS];                 // 0.5*||t||^2/var * log2e
__device__ float  g_sii[B_ROWS];                 // diagonal, nats
__device__ float  g_m[NSPLIT][B_ROWS];           // log2 units
__device__ float  g_l[NSPLIT][B_ROWS];
__device__ double g_part[32];
__device__ unsigned g_cnt;

// ---- helpers ----
__device__ __forceinline__ uint32_t smem_u32(const void* p) {
    uint32_t a;
    asm("{ .reg .u64 t; cvta.to.shared.u64 t, %1; cvt.u32.u64 %0, t; }" : "=r"(a) : "l"(p));
    return a;
}
__device__ __forceinline__ float ex2f(float x) {
    float r; asm("ex2.approx.f32 %0, %1;" : "=f"(r) : "f"(x)); return r;
}
__device__ __forceinline__ float lg2f(float x) {
    float r; asm("lg2.approx.f32 %0, %1;" : "=f"(r) : "f"(x)); return r;
}
__device__ __forceinline__ void ldsm4(uint32_t* r, uint32_t addr) {
    asm volatile("ldmatrix.sync.aligned.m8n8.x4.shared.b16 {%0,%1,%2,%3}, [%4];"
                 : "=r"(r[0]), "=r"(r[1]), "=r"(r[2]), "=r"(r[3]) : "r"(addr));
}
__device__ __forceinline__ void mma_bf16(float* d, const uint32_t* a, const uint32_t* b) {
    asm volatile(
        "mma.sync.aligned.m16n8k16.row.col.f32.bf16.bf16.f32 "
        "{%0,%1,%2,%3}, {%4,%5,%6,%7}, {%8,%9}, {%0,%1,%2,%3};"
        : "+f"(d[0]), "+f"(d[1]), "+f"(d[2]), "+f"(d[3])
        : "r"(a[0]), "r"(a[1]), "r"(a[2]), "r"(a[3]), "r"(b[0]), "r"(b[1]));
}
__device__ __forceinline__ void cp16(uint32_t dst, const void* src) {
    asm volatile("cp.async.cg.shared.global [%0], [%1], 16;" :: "r"(dst), "l"(src));
}
#define CP_COMMIT() asm volatile("cp.async.commit_group;" ::: "memory")
#define CP_WAIT(n)  asm volatile("cp.async.wait_group %0;" :: "n"(n) : "memory")

// ---------------------------------------------------------------------------
// Kernel 1: bf16-rounded copies; t2l + s_ii from the ROUNDED values.
__global__ void prep_kernel(const float* __restrict__ pred,
                            const float* __restrict__ target,
                            const float* __restrict__ sigma_p) {
    if (blockIdx.x == 0 && threadIdx.x == 0) g_cnt = 0;
    int row  = blockIdx.x * 8 + (threadIdx.x >> 5);
    int lane = threadIdx.x & 31;
    const float4* t4 = (const float4*)(target + (size_t)row * D_DIM);
    const float4* p4 = (const float4*)(pred   + (size_t)row * D_DIM);
    __nv_bfloat162* ph = (__nv_bfloat162*)(g_predh + (size_t)row * D_DIM);
    __nv_bfloat162* th = (__nv_bfloat162*)(g_targh + (size_t)row * D_DIM);
    float t2 = 0.f, dp = 0.f;
    #pragma unroll
    for (int i = lane; i < D_DIM / 4; i += 32) {
        float4 t = t4[i]; float4 p = p4[i];
        __nv_bfloat162 p0 = __floats2bfloat162_rn(p.x, p.y);
        __nv_bfloat162 p1 = __floats2bfloat162_rn(p.z, p.w);
        __nv_bfloat162 t0 = __floats2bfloat162_rn(t.x, t.y);
        __nv_bfloat162 t1 = __floats2bfloat162_rn(t.z, t.w);
        ph[i * 2] = p0; ph[i * 2 + 1] = p1;
        th[i * 2] = t0; th[i * 2 + 1] = t1;
        float tx = __bfloat162float(t0.x), ty = __bfloat162float(t0.y);
        float tz = __bfloat162float(t1.x), tw = __bfloat162float(t1.y);
        float px = __bfloat162float(p0.x), py = __bfloat162float(p0.y);
        float pz = __bfloat162float(p1.x), pw = __bfloat162float(p1.y);
        t2 += tx*tx + ty*ty + tz*tz + tw*tw;
        dp += px*tx + py*ty + pz*tz + pw*tw;
    }
    #pragma unroll
    for (int o = 16; o > 0; o >>= 1) {
        t2 += __shfl_xor_sync(0xffffffffu, t2, o);
        dp += __shfl_xor_sync(0xffffffffu, dp, o);
    }
    if (lane == 0) {
        float sig = *sigma_p;
        float inv_var = 1.0f / (sig * sig);
        g_t2l[row] = 0.5f * t2 * inv_var * LOG2E;          // log2 units
        g_sii[row] = (dp - 0.5f * t2) * inv_var;           // nats
    }
}

// ---------------------------------------------------------------------------
// Kernel 2: bf16 mma GEMM + fused online LSE (log2 domain).
// A resident in smem (full K), B 3-stage cp.async ring, register-resident
// running (m,l) per thread (no smem merge, no extra barriers).
__global__ __launch_bounds__(128, 2)
void lse_mma_kernel(const float* __restrict__ sigma_p) {
    extern __shared__ __align__(16) float dsm[];
    const uint32_t sb = smem_u32(dsm);

    const int tid  = threadIdx.x;
    const int wid  = tid >> 5;
    const int lane = tid & 31;
    const int wr = wid >> 1;        // 0..1: rows wr*64..+64
    const int wc = wid & 1;         // 0..1: cols wc*64..+64
    const int g  = lane >> 2;
    const int t  = lane & 3;
    const int row0  = blockIdx.x * BM;
    const int jbase = blockIdx.y * (B_ROWS / JSPLIT);

    const float sig = *sigma_p;
    const float invvar2 = (1.0f / (sig * sig)) * LOG2E;

    const int mat = lane >> 3;
    const int lr  = lane & 7;
    const uint32_t rowAoff = (uint32_t)((wr * 64 + (mat & 1) * 8 + lr) * 128);
    const uint32_t rowBoff = (uint32_t)((wc * 64 + (mat >> 1) * 8 + lr) * 128);
    uint32_t colA_sw[4], colB_sw[4];
    #pragma unroll
    for (int ks = 0; ks < 4; ks++) {
        colA_sw[ks] = (uint32_t)(((ks * 2 + (mat >> 1)) << 4) ^ (lr << 4));
        colB_sw[ks] = (uint32_t)(((ks * 2 + (mat & 1)) << 4) ^ (lr << 4));
    }

    uint32_t stB[3];
    #pragma unroll
    for (int s = 0; s < 3; s++) stB[s] = sb + A_BYTES + s * STAGE_B;

    // cp.async mapping: 1024 x 16B units per 16KB block, 8 per thread
    int ldr[8], ldc[8];
    uint32_t dst_off[8];
    #pragma unroll
    for (int q = 0; q < 8; q++) {
        int idx = tid + q * 128;
        ldr[q] = idx >> 3;
        ldc[q] = idx & 7;
        uint32_t off = (uint32_t)(ldr[q] * 128 + ldc[q] * 16);
        dst_off[q] = off ^ (((uint32_t)(ldr[q] & 7)) << 4);
    }

    const __nv_bfloat16* pA = g_predh + (size_t)row0 * D_DIM;

    auto issueB = [&](int c, uint32_t Bu) {
        int kcc = c & (NKC - 1);
        const __nv_bfloat16* pBc =
            g_targh + (size_t)(jbase + (c >> 2) * BN) * D_DIM + kcc * BK;
        #pragma unroll
        for (int q = 0; q < 8; q++)
            cp16(Bu + dst_off[q], pBc + (size_t)ldr[q] * D_DIM + ldc[q] * 8);
        CP_COMMIT();
    };

    // G0: entire A (4 chunks) + B0
    #pragma unroll
    for (int ci = 0; ci < 4; ci++)
        #pragma unroll
        for (int q = 0; q < 8; q++)
            cp16(sb + ci * 16384 + dst_off[q],
                 pA + ci * BK + (size_t)ldr[q] * D_DIM + ldc[q] * 8);
    {
        const __nv_bfloat16* pB0 = g_targh + (size_t)jbase * D_DIM;
        #pragma unroll
        for (int q = 0; q < 8; q++)
            cp16(stB[0] + dst_off[q], pB0 + (size_t)ldr[q] * D_DIM + ldc[q] * 8);
    }
    CP_COMMIT();          // G0
    issueB(1, stB[1]);    // G1

    // running per-thread (m, l) for 8 rows, log2 domain
    float mrow[8], lrow[8];
    #pragma unroll
    for (int i = 0; i < 8; i++) { mrow[i] = -INFINITY; lrow[i] = 0.0f; }

    for (int jt = 0; jt < NJT; jt++) {
        const int col0 = jbase + jt * BN;

        float acc[4][8][4];
        #pragma unroll
        for (int mf = 0; mf < 4; mf++)
            #pragma unroll
            for (int nf = 0; nf < 8; nf++)
                #pragma unroll
                for (int e = 0; e < 4; e++) acc[mf][nf][e] = 0.0f;

        #pragma unroll
        for (int kc = 0; kc < NKC; kc++) {
            const int cg = jt * NKC + kc;
            if (cg == NCHUNK - 1) { CP_WAIT(0); } else { CP_WAIT(1); }
            __syncthreads();
            if (cg + 2 < NCHUNK) issueB(cg + 2, stB[(cg + 2) % 3]);

            const uint32_t aB = sb + (uint32_t)((cg & 3) * 16384) + rowAoff;
            const uint32_t bB = stB[cg % 3] + rowBoff;
            #pragma unroll
            for (int ks = 0; ks < 4; ks++) {
                uint32_t af[4][4], bf[4][4];
                #pragma unroll
                for (int mf = 0; mf < 4; mf++)
                    ldsm4(af[mf], aB + (uint32_t)(mf * 2048) + colA_sw[ks]);
                #pragma unroll
                for (int np = 0; np < 4; np++)
                    ldsm4(bf[np], bB + (uint32_t)(np * 2048) + colB_sw[ks]);
                #pragma unroll
                for (int mf = 0; mf < 4; mf++)
                    #pragma unroll
                    for (int nf = 0; nf < 8; nf++)
                        mma_bf16(acc[mf][nf], af[mf], &bf[nf >> 1][(nf & 1) * 2]);
            }
        }

        // ---- epilogue: fused online LSE (log2 domain, register-resident) ----
        float tv[16];
        #pragma unroll
        for (int nf = 0; nf < 8; nf++)
            #pragma unroll
            for (int w = 0; w < 2; w++)
                tv[nf * 2 + w] = g_t2l[col0 + wc * 64 + nf * 8 + 2 * t + w];

        #pragma unroll
        for (int mf = 0; mf < 4; mf++) {
            #pragma unroll
            for (int h = 0; h < 2; h++) {
                float sv[16];
                float mx = -INFINITY;
                #pragma unroll
                for (int nf = 0; nf < 8; nf++)
                    #pragma unroll
                    for (int w = 0; w < 2; w++) {
                        float s = fmaf(acc[mf][nf][h * 2 + w], invvar2, -tv[nf * 2 + w]);
                        sv[nf * 2 + w] = s;
                        mx = fmaxf(mx, s);
                    }
                mx = fmaxf(mx, __shfl_xor_sync(0xffffffffu, mx, 1));
                mx = fmaxf(mx, __shfl_xor_sync(0xffffffffu, mx, 2));
                float sum = 0.0f;
                #pragma unroll
                for (int c = 0; c < 16; c++) sum += ex2f(sv[c] - mx);
                sum += __shfl_xor_sync(0xffffffffu, sum, 1);
                sum += __shfl_xor_sync(0xffffffffu, sum, 2);
                const int idx = mf * 2 + h;
                float mo = mrow[idx];
                float mn = fmaxf(mo, mx);
                lrow[idx] = lrow[idx] * ex2f(mo - mn) + sum * ex2f(mx - mn);
                mrow[idx] = mn;
            }
        }
    }

    if (t == 0) {
        const int split = blockIdx.y * 2 + wc;
        #pragma unroll
        for (int idx = 0; idx < 8; idx++) {
            int row = row0 + wr * 64 + (idx >> 1) * 16 + (idx & 1) * 8 + g;
            g_m[split][row] = mrow[idx];
            g_l[split][row] = lrow[idx];
        }
    }
}

// ---------------------------------------------------------------------------
// Kernel 3: per-row merge of 64 splits (log2 domain), deterministic reduce,
// last block does the fixed-order final combine.
__global__ void reduce_kernel(const float* __restrict__ sigma_p,
                              float* __restrict__ out) {
    __shared__ double sdata[256];
    int i = blockIdx.x * 256 + threadIdx.x;
    double acc;
    {
        float mmax = -INFINITY;
        #pragma unroll
        for (int s = 0; s < NSPLIT; s++) mmax = fmaxf(mmax, g_m[s][i]);
        float l = 0.0f;
        #pragma unroll
        for (int s = 0; s < NSPLIT; s++) l += g_l[s][i] * ex2f(g_m[s][i] - mmax);
        float lse = (mmax + lg2f(l)) * LN2;   // back to nats
        acc = (double)(lse - g_sii[i]);
    }
    sdata[threadIdx.x] = acc;
    __syncthreads();
    #pragma unroll
    for (int s = 128; s > 0; s >>= 1) {
        if (threadIdx.x < s) sdata[threadIdx.x] += sdata[threadIdx.x + s];
        __syncthreads();
    }
    if (threadIdx.x == 0) {
        g_part[blockIdx.x] = sdata[0];
        __threadfence();
        unsigned old = atomicAdd(&g_cnt, 1u);
        if (old == 31u) {
            double s = 0.0;
            #pragma unroll
            for (int b = 0; b < 32; b++) s += g_part[b];
            float sig = *sigma_p;
            double scale = 2.0 * (double)sig * (double)sig / (double)B_ROWS;
            out[0] = (float)(s * scale);
        }
    }
}

// ---------------------------------------------------------------------------
extern "C" void kernel_launch(void* const* d_in, const int* in_sizes, int n_in,
                              void* d_out, int out_size) {
    const float* pred   = (const float*)d_in[0];
    const float* target = (const float*)d_in[1];
    const float* sigma  = (const float*)d_in[2];
    float* out = (float*)d_out;

    cudaFuncSetAttribute(lse_mma_kernel, cudaFuncAttributeMaxDynamicSharedMemorySize, SMEM_REQ);

    prep_kernel<<<B_ROWS / 8, 256>>>(pred, target, sigma);
    lse_mma_kernel<<<dim3(B_ROWS / BM, JSPLIT), 128, SMEM_REQ>>>(sigma);
    reduce_kernel<<<32, 256>>>(sigma, out);
}

// round 9
// speedup vs baseline: 9.7398x; 1.0200x over previous
#include <cuda_runtime.h>
#include <cuda_bf16.h>
#include <math.h>
#include <stdint.h>

#define B_ROWS 8192
#define D_DIM  256
#define JSPLIT 64                        // one 128-col j-tile per split
#define NSPLIT 64
#define BM 128
#define BN 128
#define BK 64
#define NCHUNK (D_DIM / BK)              // 4 chunks per CTA
#define STAGE_MAT_B (BM * BK * 2)        // 16384 bytes per matrix stage
#define STAGE_B     (2 * STAGE_MAT_B)    // A+B per stage = 32768
#define SMEM_REQ    (3 * STAGE_B + 1024) // 96KB ring + align pad
#define LOG2E 1.4426950408889634f
#define LN2   0.6931471805599453f

// ---- device scratch ----
__device__ __nv_bfloat16 g_predh[B_ROWS * D_DIM];
__device__ __nv_bfloat16 g_targh[B_ROWS * D_DIM];
__device__ float  g_t2l[B_ROWS];                 // 0.5*||t||^2/var * log2e
__device__ float  g_sii[B_ROWS];                 // diagonal, nats
__device__ float  g_m[NSPLIT][B_ROWS];           // log2 units
__device__ float  g_l[NSPLIT][B_ROWS];
__device__ double g_part[32];
__device__ unsigned g_cnt;

// ---- helpers ----
__device__ __forceinline__ uint32_t smem_u32(const void* p) {
    uint32_t a;
    asm("{ .reg .u64 t; cvta.to.shared.u64 t, %1; cvt.u32.u64 %0, t; }" : "=r"(a) : "l"(p));
    return a;
}
__device__ __forceinline__ float ex2f(float x) {
    float r; asm("ex2.approx.f32 %0, %1;" : "=f"(r) : "f"(x)); return r;
}
__device__ __forceinline__ float lg2f(float x) {
    float r; asm("lg2.approx.f32 %0, %1;" : "=f"(r) : "f"(x)); return r;
}
__device__ __forceinline__ void ldsm4(uint32_t* r, uint32_t addr) {
    asm volatile("ldmatrix.sync.aligned.m8n8.x4.shared.b16 {%0,%1,%2,%3}, [%4];"
                 : "=r"(r[0]), "=r"(r[1]), "=r"(r[2]), "=r"(r[3]) : "r"(addr));
}
__device__ __forceinline__ void mma_bf16(float* d, const uint32_t* a, const uint32_t* b) {
    asm volatile(
        "mma.sync.aligned.m16n8k16.row.col.f32.bf16.bf16.f32 "
        "{%0,%1,%2,%3}, {%4,%5,%6,%7}, {%8,%9}, {%0,%1,%2,%3};"
        : "+f"(d[0]), "+f"(d[1]), "+f"(d[2]), "+f"(d[3])
        : "r"(a[0]), "r"(a[1]), "r"(a[2]), "r"(a[3]), "r"(b[0]), "r"(b[1]));
}
__device__ __forceinline__ void cp16(uint32_t dst, const void* src) {
    asm volatile("cp.async.cg.shared.global [%0], [%1], 16;" :: "r"(dst), "l"(src));
}
#define CP_COMMIT() asm volatile("cp.async.commit_group;" ::: "memory")
#define CP_WAIT(n)  asm volatile("cp.async.wait_group %0;" :: "n"(n) : "memory")

// ---------------------------------------------------------------------------
// Kernel 1: bf16-rounded copies; t2l + s_ii from the ROUNDED values.
__global__ void prep_kernel(const float* __restrict__ pred,
                            const float* __restrict__ target,
                            const float* __restrict__ sigma_p) {
    if (blockIdx.x == 0 && threadIdx.x == 0) g_cnt = 0;
    int row  = blockIdx.x * 8 + (threadIdx.x >> 5);
    int lane = threadIdx.x & 31;
    const float4* t4 = (const float4*)(target + (size_t)row * D_DIM);
    const float4* p4 = (const float4*)(pred   + (size_t)row * D_DIM);
    __nv_bfloat162* ph = (__nv_bfloat162*)(g_predh + (size_t)row * D_DIM);
    __nv_bfloat162* th = (__nv_bfloat162*)(g_targh + (size_t)row * D_DIM);
    float t2 = 0.f, dp = 0.f;
    #pragma unroll
    for (int i = lane; i < D_DIM / 4; i += 32) {
        float4 t = t4[i]; float4 p = p4[i];
        __nv_bfloat162 p0 = __floats2bfloat162_rn(p.x, p.y);
        __nv_bfloat162 p1 = __floats2bfloat162_rn(p.z, p.w);
        __nv_bfloat162 t0 = __floats2bfloat162_rn(t.x, t.y);
        __nv_bfloat162 t1 = __floats2bfloat162_rn(t.z, t.w);
        ph[i * 2] = p0; ph[i * 2 + 1] = p1;
        th[i * 2] = t0; th[i * 2 + 1] = t1;
        float tx = __bfloat162float(t0.x), ty = __bfloat162float(t0.y);
        float tz = __bfloat162float(t1.x), tw = __bfloat162float(t1.y);
        float px = __bfloat162float(p0.x), py = __bfloat162float(p0.y);
        float pz = __bfloat162float(p1.x), pw = __bfloat162float(p1.y);
        t2 += tx*tx + ty*ty + tz*tz + tw*tw;
        dp += px*tx + py*ty + pz*tz + pw*tw;
    }
    #pragma unroll
    for (int o = 16; o > 0; o >>= 1) {
        t2 += __shfl_xor_sync(0xffffffffu, t2, o);
        dp += __shfl_xor_sync(0xffffffffu, dp, o);
    }
    if (lane == 0) {
        float sig = *sigma_p;
        float inv_var = 1.0f / (sig * sig);
        g_t2l[row] = 0.5f * t2 * inv_var * LOG2E;
        g_sii[row] = (dp - 0.5f * t2) * inv_var;
    }
}

// ---------------------------------------------------------------------------
// Kernel 2: bf16 mma GEMM + fused online LSE (log2 domain).
// Grid (64 row-tiles, 64 j-tiles) — 4096 CTAs, 13.84 waves at 2 CTAs/SM.
// A+B 3-stage cp.async ring; per-tile (m,l) in registers; wc-halves merged
// via a 2KB smem overlay on a retired ring stage.
__global__ __launch_bounds__(128, 2)
void lse_mma_kernel(const float* __restrict__ sigma_p) {
    extern __shared__ __align__(16) float dsm[];
    uint32_t raw = smem_u32(dsm);
    uint32_t sb  = (raw + 1023u) & ~1023u;
    char* gb = (char*)dsm + (sb - raw);

    // merge overlay on ring stage 1 (dead after chunk 1; safe post-epilogue STS)
    float* pmb = (float*)(gb + STAGE_B);          // [2][128]
    float* plb = (float*)(gb + STAGE_B + 1024);

    const int tid  = threadIdx.x;
    const int wid  = tid >> 5;
    const int lane = tid & 31;
    const int wr = wid >> 1;        // 0..1: rows wr*64..+64
    const int wc = wid & 1;         // 0..1: cols wc*64..+64
    const int g  = lane >> 2;
    const int t  = lane & 3;
    const int row0 = blockIdx.x * BM;
    const int col0 = blockIdx.y * BN;

    const float sig = *sigma_p;
    const float invvar2 = (1.0f / (sig * sig)) * LOG2E;

    const int mat = lane >> 3;
    const int lr  = lane & 7;
    const uint32_t rowAoff = (uint32_t)((wr * 64 + (mat & 1) * 8 + lr) * 128);
    const uint32_t rowBoff = (uint32_t)((wc * 64 + (mat >> 1) * 8 + lr) * 128);
    uint32_t colA_sw[4], colB_sw[4];
    #pragma unroll
    for (int ks = 0; ks < 4; ks++) {
        colA_sw[ks] = (uint32_t)(((ks * 2 + (mat >> 1)) << 4) ^ (lr << 4));
        colB_sw[ks] = (uint32_t)(((ks * 2 + (mat & 1)) << 4) ^ (lr << 4));
    }

    uint32_t stA[3], stB[3];
    #pragma unroll
    for (int s = 0; s < 3; s++) {
        stA[s] = sb + s * STAGE_B;
        stB[s] = sb + s * STAGE_B + STAGE_MAT_B;
    }

    // cp.async mapping: 1024 x 16B units per matrix stage, 8 per thread
    int ldr[8], ldc[8];
    uint32_t dst_off[8];
    #pragma unroll
    for (int q = 0; q < 8; q++) {
        int idx = tid + q * 128;
        ldr[q] = idx >> 3;
        ldc[q] = idx & 7;
        uint32_t off = (uint32_t)(ldr[q] * 128 + ldc[q] * 16);
        dst_off[q] = off ^ (((uint32_t)(ldr[q] & 7)) << 4);
    }

    const __nv_bfloat16* pA = g_predh + (size_t)row0 * D_DIM;
    const __nv_bfloat16* pB = g_targh + (size_t)col0 * D_DIM;

    auto issue = [&](int c, uint32_t Au, uint32_t Bu) {
        const __nv_bfloat16* pAc = pA + c * BK;
        const __nv_bfloat16* pBc = pB + c * BK;
        #pragma unroll
        for (int q = 0; q < 8; q++)
            cp16(Au + dst_off[q], pAc + (size_t)ldr[q] * D_DIM + ldc[q] * 8);
        #pragma unroll
        for (int q = 0; q < 8; q++)
            cp16(Bu + dst_off[q], pBc + (size_t)ldr[q] * D_DIM + ldc[q] * 8);
        CP_COMMIT();
    };

    issue(0, stA[0], stB[0]);
    issue(1, stA[1], stB[1]);

    float acc[4][8][4];
    #pragma unroll
    for (int mf = 0; mf < 4; mf++)
        #pragma unroll
        for (int nf = 0; nf < 8; nf++)
            #pragma unroll
            for (int e = 0; e < 4; e++) acc[mf][nf][e] = 0.0f;

    #pragma unroll
    for (int kc = 0; kc < NCHUNK; kc++) {
        if (kc == NCHUNK - 1) { CP_WAIT(0); } else { CP_WAIT(1); }
        __syncthreads();
        if (kc + 2 < NCHUNK) issue(kc + 2, stA[(kc + 2) % 3], stB[(kc + 2) % 3]);

        const uint32_t aB = stA[kc % 3] + rowAoff;
        const uint32_t bB = stB[kc % 3] + rowBoff;
        #pragma unroll
        for (int ks = 0; ks < 4; ks++) {
            uint32_t af[4][4], bf[4][4];
            #pragma unroll
            for (int mf = 0; mf < 4; mf++)
                ldsm4(af[mf], aB + (uint32_t)(mf * 2048) + colA_sw[ks]);
            #pragma unroll
            for (int np = 0; np < 4; np++)
                ldsm4(bf[np], bB + (uint32_t)(np * 2048) + colB_sw[ks]);
            #pragma unroll
            for (int mf = 0; mf < 4; mf++)
                #pragma unroll
                for (int nf = 0; nf < 8; nf++)
                    mma_bf16(acc[mf][nf], af[mf], &bf[nf >> 1][(nf & 1) * 2]);
        }
    }

    // ---- epilogue: per-tile LSE in log2 domain ----
    float tv[16];
    #pragma unroll
    for (int nf = 0; nf < 8; nf++)
        #pragma unroll
        for (int w = 0; w < 2; w++)
            tv[nf * 2 + w] = g_t2l[col0 + wc * 64 + nf * 8 + 2 * t + w];

    #pragma unroll
    for (int mf = 0; mf < 4; mf++) {
        #pragma unroll
        for (int h = 0; h < 2; h++) {
            float sv[16];
            float mx = -INFINITY;
            #pragma unroll
            for (int nf = 0; nf < 8; nf++)
                #pragma unroll
                for (int w = 0; w < 2; w++) {
                    float s = fmaf(acc[mf][nf][h * 2 + w], invvar2, -tv[nf * 2 + w]);
                    sv[nf * 2 + w] = s;
                    mx = fmaxf(mx, s);
                }
            mx = fmaxf(mx, __shfl_xor_sync(0xffffffffu, mx, 1));
            mx = fmaxf(mx, __shfl_xor_sync(0xffffffffu, mx, 2));
            float sum = 0.0f;
            #pragma unroll
            for (int c = 0; c < 16; c++) sum += ex2f(sv[c] - mx);
            sum += __shfl_xor_sync(0xffffffffu, sum, 1);
            sum += __shfl_xor_sync(0xffffffffu, sum, 2);
            if (t == 0) {
                int rt = wr * 64 + mf * 16 + h * 8 + g;
                pmb[wc * BM + rt] = mx;
                plb[wc * BM + rt] = sum;
            }
        }
    }
    __syncthreads();
    {
        float m0 = pmb[tid], l0 = plb[tid];
        float m1 = pmb[BM + tid], l1 = plb[BM + tid];
        float mn = fmaxf(m0, m1);
        float l  = l0 * ex2f(m0 - mn) + l1 * ex2f(m1 - mn);
        g_m[blockIdx.y][row0 + tid] = mn;
        g_l[blockIdx.y][row0 + tid] = l;
    }
}

// ---------------------------------------------------------------------------
// Kernel 3: per-row merge of 64 splits (log2 domain), deterministic reduce,
// last block does the fixed-order final combine.
__global__ void reduce_kernel(const float* __restrict__ sigma_p,
                              float* __restrict__ out) {
    __shared__ double sdata[256];
    int i = blockIdx.x * 256 + threadIdx.x;
    double acc;
    {
        float mmax = -INFINITY;
        #pragma unroll
        for (int s = 0; s < NSPLIT; s++) mmax = fmaxf(mmax, g_m[s][i]);
        float l = 0.0f;
        #pragma unroll
        for (int s = 0; s < NSPLIT; s++) l += g_l[s][i] * ex2f(g_m[s][i] - mmax);
        float lse = (mmax + lg2f(l)) * LN2;
        acc = (double)(lse - g_sii[i]);
    }
    sdata[threadIdx.x] = acc;
    __syncthreads();
    #pragma unroll
    for (int s = 128; s > 0; s >>= 1) {
        if (threadIdx.x < s) sdata[threadIdx.x] += sdata[threadIdx.x + s];
        __syncthreads();
    }
    if (threadIdx.x == 0) {
        g_part[blockIdx.x] = sdata[0];
        __threadfence();
        unsigned old = atomicAdd(&g_cnt, 1u);
        if (old == 31u) {
            double s = 0.0;
            #pragma unroll
            for (int b = 0; b < 32; b++) s += g_part[b];
            float sig = *sigma_p;
            double scale = 2.0 * (double)sig * (double)sig / (double)B_ROWS;
            out[0] = (float)(s * scale);
        }
    }
}

// ---------------------------------------------------------------------------
extern "C" void kernel_launch(void* const* d_in, const int* in_sizes, int n_in,
                              void* d_out, int out_size) {
    const float* pred   = (const float*)d_in[0];
    const float* target = (const float*)d_in[1];
    const float* sigma  = (const float*)d_in[2];
    float* out = (float*)d_out;

    cudaFuncSetAttribute(lse_mma_kernel, cudaFuncAttributeMaxDynamicSharedMemorySize, SMEM_REQ);

    prep_kernel<<<B_ROWS / 8, 256>>>(pred, target, sigma);
    lse_mma_kernel<<<dim3(B_ROWS / BM, JSPLIT), 128, SMEM_REQ>>>(sigma);
    reduce_kernel<<<32, 256>>>(sigma, out);
}